// round 1
// baseline (speedup 1.0000x reference)
#include <cuda_runtime.h>
#include <cstddef>

// Problem constants
#define Bc 2
#define Sc 2048
#define Ec 1024
#define Hc 16
#define Dc 64
#define M_TOT (Bc*Sc)          // 4096 rows for the projection GEMMs

// Scratch (device globals: no allocation allowed in kernel_launch)
__device__ float g_qh[(size_t)Bc*Hc*Sc*Dc];   // [b,h,s,d]
__device__ float g_kh[(size_t)Bc*Hc*Sc*Dc];
__device__ float g_vh[(size_t)Bc*Hc*Sc*Dc];
__device__ float g_ctx[(size_t)Bc*Sc*Ec];     // [b,s,h*d]
__device__ float g_tmp[(size_t)Bc*Sc*Ec];     // pre-LN output

// ---------------------------------------------------------------------------
// 128x128x8 fp32 GEMM, 256 threads, 8x8 per-thread tile.
// MODE 0: out[b,h,s,d] head-permuted write (QKV projections)
// MODE 1: plain row-major write (output projection)
// outsel picks the device-global destination; Ain==nullptr means A = g_ctx.
// ---------------------------------------------------------------------------
template<int MODE>
__global__ void __launch_bounds__(256) gemm128(const float* __restrict__ Ain,
                                               const float* __restrict__ W,
                                               const float* __restrict__ bias,
                                               int outsel)
{
    const float* A = Ain ? Ain : g_ctx;
    float* out = (outsel == 0) ? g_qh : (outsel == 1) ? g_kh
               : (outsel == 2) ? g_vh : g_tmp;

    __shared__ __align__(16) float As[8][132];
    __shared__ __align__(16) float Bs[8][132];

    const int tid  = threadIdx.x;
    const int crow = blockIdx.y * 128;
    const int ccol = blockIdx.x * 128;
    const int tr = tid >> 4, tc = tid & 15;
    const int arow = tid >> 1, acol = (tid & 1) * 4;
    const int brow = tid >> 5, bcol = (tid & 31) * 4;

    float acc[8][8];
#pragma unroll
    for (int i = 0; i < 8; i++)
#pragma unroll
        for (int j = 0; j < 8; j++) acc[i][j] = 0.f;

    const float* Aptr = A + (size_t)(crow + arow) * 1024 + acol;
    const float* Wptr = W + (size_t)brow * 1024 + ccol + bcol;

    for (int k0 = 0; k0 < 1024; k0 += 8) {
        float4 av = *(const float4*)(Aptr + k0);
        float4 bv = *(const float4*)(Wptr + (size_t)k0 * 1024);
        __syncthreads();
        As[acol + 0][arow] = av.x;
        As[acol + 1][arow] = av.y;
        As[acol + 2][arow] = av.z;
        As[acol + 3][arow] = av.w;
        *(float4*)&Bs[brow][bcol] = bv;
        __syncthreads();
#pragma unroll
        for (int k = 0; k < 8; k++) {
            float a[8], bb[8];
            *(float4*)(a)      = *(const float4*)&As[k][tr * 4];
            *(float4*)(a + 4)  = *(const float4*)&As[k][tr * 4 + 64];
            *(float4*)(bb)     = *(const float4*)&Bs[k][tc * 4];
            *(float4*)(bb + 4) = *(const float4*)&Bs[k][tc * 4 + 64];
#pragma unroll
            for (int i = 0; i < 8; i++)
#pragma unroll
                for (int j = 0; j < 8; j++)
                    acc[i][j] += a[i] * bb[j];
        }
    }

    float bvals[8];
#pragma unroll
    for (int jj = 0; jj < 2; jj++)
#pragma unroll
        for (int j = 0; j < 4; j++)
            bvals[jj * 4 + j] = bias[ccol + tc * 4 + jj * 64 + j];

#pragma unroll
    for (int ii = 0; ii < 2; ii++)
#pragma unroll
    for (int i = 0; i < 4; i++) {
        const int row = crow + tr * 4 + ii * 64 + i;
#pragma unroll
        for (int jj = 0; jj < 2; jj++) {
            const int col = ccol + tc * 4 + jj * 64;
            float4 v;
            v.x = acc[ii * 4 + i][jj * 4 + 0] + bvals[jj * 4 + 0];
            v.y = acc[ii * 4 + i][jj * 4 + 1] + bvals[jj * 4 + 1];
            v.z = acc[ii * 4 + i][jj * 4 + 2] + bvals[jj * 4 + 2];
            v.w = acc[ii * 4 + i][jj * 4 + 3] + bvals[jj * 4 + 3];
            if (MODE == 1) {
                *(float4*)(out + (size_t)row * 1024 + col) = v;
            } else {
                const int b = row >> 11, s = row & 2047;
                const int h = col >> 6,  d = col & 63;
                *(float4*)(out + ((((size_t)b * Hc + h) * Sc + s) << 6) + d) = v;
            }
        }
    }
}

// ---------------------------------------------------------------------------
// Fused attention: per block = one (b,h) and 8 query rows.
// scores (causal-skipped tiles) -> smem row buffer -> softmax in place ->
// coalesced attn write (+ zero fill) -> attn @ V from smem tiles -> ctx.
// ---------------------------------------------------------------------------
#define ROWS 8
#define JT   128
#define KST  68   // padded smem row stride (floats), 16B-aligned rows
#define ATTN_SMEM ((ROWS*Sc + JT*KST + ROWS*Dc) * 4)

__global__ void __launch_bounds__(256) attn_kernel(const int* __restrict__ isM,
                                                   float* __restrict__ attn_out)
{
    extern __shared__ float sm[];
    float* sc = sm;                    // ROWS * Sc scores / probs
    float* kv = sm + ROWS * Sc;        // JT * KST staging tile (K then V)
    float* qs = kv + JT * KST;         // ROWS * Dc query rows

    const int i0  = blockIdx.x * ROWS;
    const int h   = blockIdx.y;
    const int b   = blockIdx.z;
    const int tid = threadIdx.x;
    const int masked = *isM;

    const size_t bh = (size_t)b * Hc + h;
    const float* Q = g_qh + bh * Sc * Dc;
    const float* K = g_kh + bh * Sc * Dc;
    const float* V = g_vh + bh * Sc * Dc;

    // load 8 query rows (contiguous 512 floats)
    for (int idx = tid; idx < ROWS * Dc; idx += 256)
        qs[idx] = Q[(size_t)i0 * Dc + idx];

    const int lim = masked ? (i0 + ROWS) : Sc;
    int njc = ((lim + JT - 1) / JT) * JT;
    if (njc > Sc) njc = Sc;

    const int r = tid >> 6;      // 0..3 -> rows r and r+4
    const int c = tid & 63;      // cols c and c+64 within tile

    // ---- scores ----
    for (int jt = 0; jt < njc; jt += JT) {
        __syncthreads();
        for (int idx = tid; idx < JT * Dc; idx += 256)
            kv[(idx >> 6) * KST + (idx & 63)] = K[((size_t)jt << 6) + idx];
        __syncthreads();

        float s00 = 0.f, s01 = 0.f, s10 = 0.f, s11 = 0.f;
        const float4* q0 = (const float4*)(qs + r * Dc);
        const float4* q1 = (const float4*)(qs + (r + 4) * Dc);
        const float4* k0 = (const float4*)(kv + c * KST);
        const float4* k1 = (const float4*)(kv + (c + 64) * KST);
#pragma unroll
        for (int d4 = 0; d4 < Dc / 4; d4++) {
            float4 a0 = q0[d4], a1 = q1[d4];
            float4 b0 = k0[d4], b1 = k1[d4];
            s00 += a0.x*b0.x + a0.y*b0.y + a0.z*b0.z + a0.w*b0.w;
            s01 += a0.x*b1.x + a0.y*b1.y + a0.z*b1.z + a0.w*b1.w;
            s10 += a1.x*b0.x + a1.y*b0.y + a1.z*b0.z + a1.w*b0.w;
            s11 += a1.x*b1.x + a1.y*b1.y + a1.z*b1.z + a1.w*b1.w;
        }
        const int ir0 = i0 + r, ir1 = i0 + r + 4;
        const int j0 = jt + c,  j1 = jt + c + 64;
        s00 *= 0.125f; s01 *= 0.125f; s10 *= 0.125f; s11 *= 0.125f;
        if (masked) {
            if (j0 > ir0) s00 = -1e9f;
            if (j1 > ir0) s01 = -1e9f;
            if (j0 > ir1) s10 = -1e9f;
            if (j1 > ir1) s11 = -1e9f;
        }
        sc[r * Sc + j0] = s00;       sc[r * Sc + j1] = s01;
        sc[(r + 4) * Sc + j0] = s10; sc[(r + 4) * Sc + j1] = s11;
    }
    __syncthreads();

    // ---- softmax: warp w owns row w ----
    {
        const int w = tid >> 5, lane = tid & 31;
        float* row = sc + w * Sc;
        float m = -3.4e38f;
        for (int j = lane; j < njc; j += 32) m = fmaxf(m, row[j]);
#pragma unroll
        for (int o = 16; o; o >>= 1) m = fmaxf(m, __shfl_xor_sync(0xffffffffu, m, o));
        float s = 0.f;
        for (int j = lane; j < njc; j += 32) {
            float e = __expf(row[j] - m);
            row[j] = e;
            s += e;
        }
#pragma unroll
        for (int o = 16; o; o >>= 1) s += __shfl_xor_sync(0xffffffffu, s, o);
        const float inv = 1.f / s;
        const size_t abase = (bh * Sc + (size_t)(i0 + w)) * Sc;
        for (int j = lane; j < njc; j += 32) {
            float p = row[j] * inv;
            row[j] = p;
            attn_out[abase + j] = p;
        }
        for (int j = njc + lane; j < Sc; j += 32)
            attn_out[abase + j] = 0.f;
    }
    __syncthreads();

    // ---- ctx = attn @ V ----
    float acc0 = 0.f, acc1 = 0.f;
    for (int jt = 0; jt < njc; jt += JT) {
        __syncthreads();
        for (int idx = tid; idx < JT * Dc; idx += 256)
            kv[(idx >> 6) * KST + (idx & 63)] = V[((size_t)jt << 6) + idx];
        __syncthreads();
        const float4* p0 = (const float4*)(sc + r * Sc + jt);
        const float4* p1 = (const float4*)(sc + (r + 4) * Sc + jt);
#pragma unroll 4
        for (int c4 = 0; c4 < JT / 4; c4++) {
            float4 pa = p0[c4], pb = p1[c4];
            float v0 = kv[(c4 * 4 + 0) * KST + c];
            float v1 = kv[(c4 * 4 + 1) * KST + c];
            float v2 = kv[(c4 * 4 + 2) * KST + c];
            float v3 = kv[(c4 * 4 + 3) * KST + c];
            acc0 += pa.x * v0 + pa.y * v1 + pa.z * v2 + pa.w * v3;
            acc1 += pb.x * v0 + pb.y * v1 + pb.z * v2 + pb.w * v3;
        }
    }
    // write ctx in [b,s,h*64+d] layout (row-major for the out-proj GEMM)
    const size_t cb = (size_t)b * Sc * Ec + (size_t)h * Dc;
    g_ctx[cb + (size_t)(i0 + r) * Ec + c]     = acc0;
    g_ctx[cb + (size_t)(i0 + r + 4) * Ec + c] = acc1;
}

// ---------------------------------------------------------------------------
// Residual + LayerNorm: one block per row of 1024.
// ---------------------------------------------------------------------------
__global__ void __launch_bounds__(256) ln_kernel(const float* __restrict__ qin,
                                                 float* __restrict__ out)
{
    const size_t row = blockIdx.x;
    const int tid = threadIdx.x;
    float4 x  = *(const float4*)(g_tmp + row * 1024 + tid * 4);
    float4 qq = *(const float4*)(qin   + row * 1024 + tid * 4);
    x.x += qq.x; x.y += qq.y; x.z += qq.z; x.w += qq.w;

    float s  = x.x + x.y + x.z + x.w;
    float s2 = x.x*x.x + x.y*x.y + x.z*x.z + x.w*x.w;

    __shared__ float rs[8], rs2[8];
    const int w = tid >> 5, lane = tid & 31;
#pragma unroll
    for (int o = 16; o; o >>= 1) {
        s  += __shfl_xor_sync(0xffffffffu, s,  o);
        s2 += __shfl_xor_sync(0xffffffffu, s2, o);
    }
    if (!lane) { rs[w] = s; rs2[w] = s2; }
    __syncthreads();
    if (w == 0) {
        float a  = (lane < 8) ? rs[lane]  : 0.f;
        float a2 = (lane < 8) ? rs2[lane] : 0.f;
#pragma unroll
        for (int o = 4; o; o >>= 1) {
            a  += __shfl_xor_sync(0xffffffffu, a,  o);
            a2 += __shfl_xor_sync(0xffffffffu, a2, o);
        }
        if (!lane) { rs[0] = a; rs2[0] = a2; }
    }
    __syncthreads();
    const float mu   = rs[0] * (1.f / 1024.f);
    const float var  = rs2[0] * (1.f / 1024.f) - mu * mu;
    const float rstd = rsqrtf(var + 1e-5f);
    float4 o;
    o.x = (x.x - mu) * rstd; o.y = (x.y - mu) * rstd;
    o.z = (x.z - mu) * rstd; o.w = (x.w - mu) * rstd;
    *(float4*)(out + row * 1024 + tid * 4) = o;
}

// ---------------------------------------------------------------------------
extern "C" void kernel_launch(void* const* d_in, const int* in_sizes, int n_in,
                              void* d_out, int out_size)
{
    (void)in_sizes; (void)n_in; (void)out_size;
    const float* q  = (const float*)d_in[0];
    const float* k  = (const float*)d_in[1];
    const float* v  = (const float*)d_in[2];
    const float* Wq = (const float*)d_in[3];
    const float* bq = (const float*)d_in[4];
    const float* Wk = (const float*)d_in[5];
    const float* bk = (const float*)d_in[6];
    const float* Wv = (const float*)d_in[7];
    const float* bv = (const float*)d_in[8];
    const float* Wo = (const float*)d_in[9];
    const float* bo = (const float*)d_in[10];
    const int*   isM = (const int*)d_in[11];

    float* out  = (float*)d_out;                       // outs [B,S,E]
    float* attn = out + (size_t)Bc * Sc * Ec;          // attn [B,H,S,S]

    cudaFuncSetAttribute(attn_kernel,
                         cudaFuncAttributeMaxDynamicSharedMemorySize, ATTN_SMEM);

    dim3 gg(Ec / 128, M_TOT / 128);
    gemm128<0><<<gg, 256>>>(q, Wq, bq, 0);
    gemm128<0><<<gg, 256>>>(k, Wk, bk, 1);
    gemm128<0><<<gg, 256>>>(v, Wv, bv, 2);

    attn_kernel<<<dim3(Sc / ROWS, Hc, Bc), 256, ATTN_SMEM>>>(isM, attn);

    gemm128<1><<<gg, 256>>>(nullptr, Wo, bo, 3);
    ln_kernel<<<M_TOT, 256>>>(q, out);
}

// round 2
// speedup vs baseline: 1.1449x; 1.1449x over previous
#include <cuda_runtime.h>
#include <cuda_bf16.h>
#include <cstddef>

// Problem constants
#define Bc 2
#define Sc 2048
#define Ec 1024
#define Hc 16
#define Dc 64
#define M_TOT (Bc*Sc)          // 4096 rows for the projection GEMMs

// Scratch (device globals: no allocation allowed in kernel_launch)
__device__ float g_qh[(size_t)Bc*Hc*Sc*Dc];   // [b,h,s,d]
__device__ float g_kh[(size_t)Bc*Hc*Sc*Dc];
__device__ float g_vh[(size_t)Bc*Hc*Sc*Dc];
__device__ float g_ctx[(size_t)Bc*Sc*Ec];     // [b,s,h*d]
__device__ float g_tmp[(size_t)Bc*Sc*Ec];     // pre-LN output

// ---------------------------------------------------------------------------
// Tensor-core GEMM: C[4096,1024] = A @ W + bias, fp32 in/out, internally
// 3-term bf16 split (Ahi*Whi + Ahi*Wlo + Alo*Whi) for ~1.5e-5 rel accuracy.
// BM=128, BN=128, BK=32, 256 threads (8 warps, 4x2), warp tile 32x64,
// mma.sync.m16n8k16.bf16. MODE 0: head-permuted write; MODE 1: row-major.
// ---------------------------------------------------------------------------
__device__ __forceinline__ void bf16mma(float c[4], const unsigned a[4],
                                        const unsigned b[2])
{
    asm volatile(
        "mma.sync.aligned.m16n8k16.row.col.f32.bf16.bf16.f32 "
        "{%0,%1,%2,%3}, {%4,%5,%6,%7}, {%8,%9}, {%0,%1,%2,%3};\n"
        : "+f"(c[0]), "+f"(c[1]), "+f"(c[2]), "+f"(c[3])
        : "r"(a[0]), "r"(a[1]), "r"(a[2]), "r"(a[3]), "r"(b[0]), "r"(b[1]));
}

template<int MODE>
__global__ void __launch_bounds__(256) gemm_tc(const float* __restrict__ Ain,
                                               const float* __restrict__ W,
                                               const float* __restrict__ bias,
                                               int outsel)
{
    const float* A = Ain ? Ain : g_ctx;
    float* out = (outsel == 0) ? g_qh : (outsel == 1) ? g_kh
               : (outsel == 2) ? g_vh : g_tmp;

    // A tiles: row-major [m][k], stride 40 (conflict-free fragment loads)
    __shared__ __align__(16) __nv_bfloat16 sAhi[128][40];
    __shared__ __align__(16) __nv_bfloat16 sAlo[128][40];
    // W tiles: K-major [k][n], stride 136
    __shared__ __align__(16) __nv_bfloat16 sWhi[32][136];
    __shared__ __align__(16) __nv_bfloat16 sWlo[32][136];

    const int tid  = threadIdx.x;
    const int crow = blockIdx.y * 128;
    const int ccol = blockIdx.x * 128;

    const int warp = tid >> 5, lane = tid & 31;
    const int wm0 = (warp >> 1) * 32;      // warp row offset in tile
    const int wn0 = (warp & 1) * 64;       // warp col offset in tile
    const int gid = lane >> 2;             // 0..7
    const int qid = lane & 3;              // 0..3

    // gmem load mapping
    const int ar = tid >> 1;               // 0..127
    const int ac = (tid & 1) * 16;         // 0 or 16
    const int wr = tid >> 3;               // 0..31
    const int wc = (tid & 7) * 16;         // 0..112

    const float* Ap = A + (size_t)(crow + ar) * 1024 + ac;
    const float* Wp = W + (size_t)wr * 1024 + ccol + wc;

    float acc[2][8][4];
#pragma unroll
    for (int mt = 0; mt < 2; mt++)
#pragma unroll
        for (int nt = 0; nt < 8; nt++)
#pragma unroll
            for (int e = 0; e < 4; e++) acc[mt][nt][e] = 0.f;

    for (int k0 = 0; k0 < 1024; k0 += 32) {
        __syncthreads();
        // fill A tile (with hi/lo split)
#pragma unroll
        for (int j = 0; j < 4; j++) {
            float4 v = *(const float4*)(Ap + k0 + 4 * j);
            float xs[4] = {v.x, v.y, v.z, v.w};
#pragma unroll
            for (int e = 0; e < 4; e++) {
                __nv_bfloat16 h = __float2bfloat16(xs[e]);
                sAhi[ar][ac + 4 * j + e] = h;
                sAlo[ar][ac + 4 * j + e] =
                    __float2bfloat16(xs[e] - __bfloat162float(h));
            }
        }
        // fill W tile
#pragma unroll
        for (int j = 0; j < 4; j++) {
            float4 v = *(const float4*)(Wp + (size_t)k0 * 1024 + 4 * j);
            float xs[4] = {v.x, v.y, v.z, v.w};
#pragma unroll
            for (int e = 0; e < 4; e++) {
                __nv_bfloat16 h = __float2bfloat16(xs[e]);
                sWhi[wr][wc + 4 * j + e] = h;
                sWlo[wr][wc + 4 * j + e] =
                    __float2bfloat16(xs[e] - __bfloat162float(h));
            }
        }
        __syncthreads();

#pragma unroll
        for (int ks = 0; ks < 32; ks += 16) {
            // A fragments
            unsigned ahi[2][4], alo[2][4];
#pragma unroll
            for (int mt = 0; mt < 2; mt++) {
                const int r0 = wm0 + mt * 16 + gid;
                const int cc = ks + 2 * qid;
                ahi[mt][0] = *(const unsigned*)&sAhi[r0][cc];
                ahi[mt][1] = *(const unsigned*)&sAhi[r0 + 8][cc];
                ahi[mt][2] = *(const unsigned*)&sAhi[r0][cc + 8];
                ahi[mt][3] = *(const unsigned*)&sAhi[r0 + 8][cc + 8];
                alo[mt][0] = *(const unsigned*)&sAlo[r0][cc];
                alo[mt][1] = *(const unsigned*)&sAlo[r0 + 8][cc];
                alo[mt][2] = *(const unsigned*)&sAlo[r0][cc + 8];
                alo[mt][3] = *(const unsigned*)&sAlo[r0 + 8][cc + 8];
            }
#pragma unroll
            for (int nt = 0; nt < 8; nt++) {
                const int n  = wn0 + nt * 8 + gid;
                const int kk = ks + 2 * qid;
                unsigned bhi[2], blo[2];
                bhi[0] = (unsigned)__bfloat16_as_ushort(sWhi[kk][n])
                       | ((unsigned)__bfloat16_as_ushort(sWhi[kk + 1][n]) << 16);
                bhi[1] = (unsigned)__bfloat16_as_ushort(sWhi[kk + 8][n])
                       | ((unsigned)__bfloat16_as_ushort(sWhi[kk + 9][n]) << 16);
                blo[0] = (unsigned)__bfloat16_as_ushort(sWlo[kk][n])
                       | ((unsigned)__bfloat16_as_ushort(sWlo[kk + 1][n]) << 16);
                blo[1] = (unsigned)__bfloat16_as_ushort(sWlo[kk + 8][n])
                       | ((unsigned)__bfloat16_as_ushort(sWlo[kk + 9][n]) << 16);
#pragma unroll
                for (int mt = 0; mt < 2; mt++) {
                    bf16mma(acc[mt][nt], ahi[mt], bhi);
                    bf16mma(acc[mt][nt], ahi[mt], blo);
                    bf16mma(acc[mt][nt], alo[mt], bhi);
                }
            }
        }
    }

    // epilogue: bias + write
#pragma unroll
    for (int mt = 0; mt < 2; mt++) {
#pragma unroll
        for (int nt = 0; nt < 8; nt++) {
            const int row = crow + wm0 + mt * 16 + gid;
            const int col = ccol + wn0 + nt * 8 + 2 * qid;
            const float b0 = bias[col], b1 = bias[col + 1];
            float2 v0, v1;
            v0.x = acc[mt][nt][0] + b0; v0.y = acc[mt][nt][1] + b1;
            v1.x = acc[mt][nt][2] + b0; v1.y = acc[mt][nt][3] + b1;
            if (MODE == 1) {
                *(float2*)(out + (size_t)row * 1024 + col) = v0;
                *(float2*)(out + (size_t)(row + 8) * 1024 + col) = v1;
            } else {
                const int b = row >> 11, h = col >> 6, d = col & 63;
                const int s = row & 2047;
                float* base = out + ((((size_t)b * Hc + h) * Sc) << 6) + d;
                *(float2*)(base + ((size_t)s << 6)) = v0;
                *(float2*)(base + ((size_t)(s + 8) << 6)) = v1;
            }
        }
    }
}

// ---------------------------------------------------------------------------
// Fused attention: per block = one (b,h) and 8 query rows.
// ---------------------------------------------------------------------------
#define ROWS 8
#define JT   128
#define KST  68
#define ATTN_SMEM ((ROWS*Sc + JT*KST + ROWS*Dc) * 4)

__global__ void __launch_bounds__(256) attn_kernel(const int* __restrict__ isM,
                                                   float* __restrict__ attn_out)
{
    extern __shared__ float sm[];
    float* sc = sm;
    float* kv = sm + ROWS * Sc;
    float* qs = kv + JT * KST;

    const int i0  = blockIdx.x * ROWS;
    const int h   = blockIdx.y;
    const int b   = blockIdx.z;
    const int tid = threadIdx.x;
    const int masked = *isM;

    const size_t bh = (size_t)b * Hc + h;
    const float* Q = g_qh + bh * Sc * Dc;
    const float* K = g_kh + bh * Sc * Dc;
    const float* V = g_vh + bh * Sc * Dc;

    for (int idx = tid; idx < ROWS * Dc; idx += 256)
        qs[idx] = Q[(size_t)i0 * Dc + idx];

    const int lim = masked ? (i0 + ROWS) : Sc;
    int njc = ((lim + JT - 1) / JT) * JT;
    if (njc > Sc) njc = Sc;

    const int r = tid >> 6;
    const int c = tid & 63;

    for (int jt = 0; jt < njc; jt += JT) {
        __syncthreads();
        for (int idx = tid; idx < JT * Dc; idx += 256)
            kv[(idx >> 6) * KST + (idx & 63)] = K[((size_t)jt << 6) + idx];
        __syncthreads();

        float s00 = 0.f, s01 = 0.f, s10 = 0.f, s11 = 0.f;
        const float4* q0 = (const float4*)(qs + r * Dc);
        const float4* q1 = (const float4*)(qs + (r + 4) * Dc);
        const float4* k0 = (const float4*)(kv + c * KST);
        const float4* k1 = (const float4*)(kv + (c + 64) * KST);
#pragma unroll
        for (int d4 = 0; d4 < Dc / 4; d4++) {
            float4 a0 = q0[d4], a1 = q1[d4];
            float4 b0 = k0[d4], b1 = k1[d4];
            s00 += a0.x*b0.x + a0.y*b0.y + a0.z*b0.z + a0.w*b0.w;
            s01 += a0.x*b1.x + a0.y*b1.y + a0.z*b1.z + a0.w*b1.w;
            s10 += a1.x*b0.x + a1.y*b0.y + a1.z*b0.z + a1.w*b0.w;
            s11 += a1.x*b1.x + a1.y*b1.y + a1.z*b1.z + a1.w*b1.w;
        }
        const int ir0 = i0 + r, ir1 = i0 + r + 4;
        const int j0 = jt + c,  j1 = jt + c + 64;
        s00 *= 0.125f; s01 *= 0.125f; s10 *= 0.125f; s11 *= 0.125f;
        if (masked) {
            if (j0 > ir0) s00 = -1e9f;
            if (j1 > ir0) s01 = -1e9f;
            if (j0 > ir1) s10 = -1e9f;
            if (j1 > ir1) s11 = -1e9f;
        }
        sc[r * Sc + j0] = s00;       sc[r * Sc + j1] = s01;
        sc[(r + 4) * Sc + j0] = s10; sc[(r + 4) * Sc + j1] = s11;
    }
    __syncthreads();

    {
        const int w = tid >> 5, lane = tid & 31;
        float* row = sc + w * Sc;
        float m = -3.4e38f;
        for (int j = lane; j < njc; j += 32) m = fmaxf(m, row[j]);
#pragma unroll
        for (int o = 16; o; o >>= 1) m = fmaxf(m, __shfl_xor_sync(0xffffffffu, m, o));
        float s = 0.f;
        for (int j = lane; j < njc; j += 32) {
            float e = __expf(row[j] - m);
            row[j] = e;
            s += e;
        }
#pragma unroll
        for (int o = 16; o; o >>= 1) s += __shfl_xor_sync(0xffffffffu, s, o);
        const float inv = 1.f / s;
        const size_t abase = (bh * Sc + (size_t)(i0 + w)) * Sc;
        for (int j = lane; j < njc; j += 32) {
            float p = row[j] * inv;
            row[j] = p;
            attn_out[abase + j] = p;
        }
        for (int j = njc + lane; j < Sc; j += 32)
            attn_out[abase + j] = 0.f;
    }
    __syncthreads();

    float acc0 = 0.f, acc1 = 0.f;
    for (int jt = 0; jt < njc; jt += JT) {
        __syncthreads();
        for (int idx = tid; idx < JT * Dc; idx += 256)
            kv[(idx >> 6) * KST + (idx & 63)] = V[((size_t)jt << 6) + idx];
        __syncthreads();
        const float4* p0 = (const float4*)(sc + r * Sc + jt);
        const float4* p1 = (const float4*)(sc + (r + 4) * Sc + jt);
#pragma unroll 4
        for (int c4 = 0; c4 < JT / 4; c4++) {
            float4 pa = p0[c4], pb = p1[c4];
            float v0 = kv[(c4 * 4 + 0) * KST + c];
            float v1 = kv[(c4 * 4 + 1) * KST + c];
            float v2 = kv[(c4 * 4 + 2) * KST + c];
            float v3 = kv[(c4 * 4 + 3) * KST + c];
            acc0 += pa.x * v0 + pa.y * v1 + pa.z * v2 + pa.w * v3;
            acc1 += pb.x * v0 + pb.y * v1 + pb.z * v2 + pb.w * v3;
        }
    }
    const size_t cb = (size_t)b * Sc * Ec + (size_t)h * Dc;
    g_ctx[cb + (size_t)(i0 + r) * Ec + c]     = acc0;
    g_ctx[cb + (size_t)(i0 + r + 4) * Ec + c] = acc1;
}

// ---------------------------------------------------------------------------
// Residual + LayerNorm
// ---------------------------------------------------------------------------
__global__ void __launch_bounds__(256) ln_kernel(const float* __restrict__ qin,
                                                 float* __restrict__ out)
{
    const size_t row = blockIdx.x;
    const int tid = threadIdx.x;
    float4 x  = *(const float4*)(g_tmp + row * 1024 + tid * 4);
    float4 qq = *(const float4*)(qin   + row * 1024 + tid * 4);
    x.x += qq.x; x.y += qq.y; x.z += qq.z; x.w += qq.w;

    float s  = x.x + x.y + x.z + x.w;
    float s2 = x.x*x.x + x.y*x.y + x.z*x.z + x.w*x.w;

    __shared__ float rs[8], rs2[8];
    const int w = tid >> 5, lane = tid & 31;
#pragma unroll
    for (int o = 16; o; o >>= 1) {
        s  += __shfl_xor_sync(0xffffffffu, s,  o);
        s2 += __shfl_xor_sync(0xffffffffu, s2, o);
    }
    if (!lane) { rs[w] = s; rs2[w] = s2; }
    __syncthreads();
    if (w == 0) {
        float a  = (lane < 8) ? rs[lane]  : 0.f;
        float a2 = (lane < 8) ? rs2[lane] : 0.f;
#pragma unroll
        for (int o = 4; o; o >>= 1) {
            a  += __shfl_xor_sync(0xffffffffu, a,  o);
            a2 += __shfl_xor_sync(0xffffffffu, a2, o);
        }
        if (!lane) { rs[0] = a; rs2[0] = a2; }
    }
    __syncthreads();
    const float mu   = rs[0] * (1.f / 1024.f);
    const float var  = rs2[0] * (1.f / 1024.f) - mu * mu;
    const float rstd = rsqrtf(var + 1e-5f);
    float4 o;
    o.x = (x.x - mu) * rstd; o.y = (x.y - mu) * rstd;
    o.z = (x.z - mu) * rstd; o.w = (x.w - mu) * rstd;
    *(float4*)(out + row * 1024 + tid * 4) = o;
}

// ---------------------------------------------------------------------------
extern "C" void kernel_launch(void* const* d_in, const int* in_sizes, int n_in,
                              void* d_out, int out_size)
{
    (void)in_sizes; (void)n_in; (void)out_size;
    const float* q  = (const float*)d_in[0];
    const float* k  = (const float*)d_in[1];
    const float* v  = (const float*)d_in[2];
    const float* Wq = (const float*)d_in[3];
    const float* bq = (const float*)d_in[4];
    const float* Wk = (const float*)d_in[5];
    const float* bk = (const float*)d_in[6];
    const float* Wv = (const float*)d_in[7];
    const float* bv = (const float*)d_in[8];
    const float* Wo = (const float*)d_in[9];
    const float* bo = (const float*)d_in[10];
    const int*   isM = (const int*)d_in[11];

    float* out  = (float*)d_out;                       // outs [B,S,E]
    float* attn = out + (size_t)Bc * Sc * Ec;          // attn [B,H,S,S]

    cudaFuncSetAttribute(attn_kernel,
                         cudaFuncAttributeMaxDynamicSharedMemorySize, ATTN_SMEM);

    dim3 gg(Ec / 128, M_TOT / 128);
    gemm_tc<0><<<gg, 256>>>(q, Wq, bq, 0);
    gemm_tc<0><<<gg, 256>>>(k, Wk, bk, 1);
    gemm_tc<0><<<gg, 256>>>(v, Wv, bv, 2);

    attn_kernel<<<dim3(Sc / ROWS, Hc, Bc), 256, ATTN_SMEM>>>(isM, attn);

    gemm_tc<1><<<gg, 256>>>(nullptr, Wo, bo, 3);
    ln_kernel<<<M_TOT, 256>>>(q, out);
}

// round 3
// speedup vs baseline: 2.4332x; 2.1252x over previous
#include <cuda_runtime.h>
#include <cuda_bf16.h>
#include <cstddef>

// Problem constants
#define Bc 2
#define Sc 2048
#define Ec 1024
#define Hc 16
#define Dc 64
#define M_TOT (Bc*Sc)

// Scratch (device globals)
__device__ float g_qh[(size_t)Bc*Hc*Sc*Dc];   // [b,h,s,d]
__device__ float g_kh[(size_t)Bc*Hc*Sc*Dc];
__device__ float g_vh[(size_t)Bc*Hc*Sc*Dc];
__device__ float g_ctx[(size_t)Bc*Sc*Ec];     // [b,s,h*d]
__device__ float g_tmp[(size_t)Bc*Sc*Ec];     // pre-LN output
__device__ float g_l[(size_t)Bc*Hc*Sc];       // per-row 1/sum for attn normalize

__device__ __forceinline__ void bf16mma(float c[4], const unsigned a[4],
                                        const unsigned b[2])
{
    asm volatile(
        "mma.sync.aligned.m16n8k16.row.col.f32.bf16.bf16.f32 "
        "{%0,%1,%2,%3}, {%4,%5,%6,%7}, {%8,%9}, {%0,%1,%2,%3};\n"
        : "+f"(c[0]), "+f"(c[1]), "+f"(c[2]), "+f"(c[3])
        : "r"(a[0]), "r"(a[1]), "r"(a[2]), "r"(a[3]), "r"(b[0]), "r"(b[1]));
}

__device__ __forceinline__ void splitf(float x, __nv_bfloat16& h, __nv_bfloat16& l)
{
    h = __float2bfloat16(x);
    l = __float2bfloat16(x - __bfloat162float(h));
}

// ---------------------------------------------------------------------------
// Tensor-core projection GEMM (unchanged from R2 — known good)
// ---------------------------------------------------------------------------
template<int MODE>
__global__ void __launch_bounds__(256) gemm_tc(const float* __restrict__ Ain,
                                               const float* __restrict__ W,
                                               const float* __restrict__ bias,
                                               int outsel)
{
    const float* A = Ain ? Ain : g_ctx;
    float* out = (outsel == 0) ? g_qh : (outsel == 1) ? g_kh
               : (outsel == 2) ? g_vh : g_tmp;

    __shared__ __align__(16) __nv_bfloat16 sAhi[128][40];
    __shared__ __align__(16) __nv_bfloat16 sAlo[128][40];
    __shared__ __align__(16) __nv_bfloat16 sWhi[32][136];
    __shared__ __align__(16) __nv_bfloat16 sWlo[32][136];

    const int tid  = threadIdx.x;
    const int crow = blockIdx.y * 128;
    const int ccol = blockIdx.x * 128;

    const int warp = tid >> 5, lane = tid & 31;
    const int wm0 = (warp >> 1) * 32;
    const int wn0 = (warp & 1) * 64;
    const int gid = lane >> 2;
    const int qid = lane & 3;

    const int ar = tid >> 1;
    const int ac = (tid & 1) * 16;
    const int wr = tid >> 3;
    const int wc = (tid & 7) * 16;

    const float* Ap = A + (size_t)(crow + ar) * 1024 + ac;
    const float* Wp = W + (size_t)wr * 1024 + ccol + wc;

    float acc[2][8][4];
#pragma unroll
    for (int mt = 0; mt < 2; mt++)
#pragma unroll
        for (int nt = 0; nt < 8; nt++)
#pragma unroll
            for (int e = 0; e < 4; e++) acc[mt][nt][e] = 0.f;

    for (int k0 = 0; k0 < 1024; k0 += 32) {
        __syncthreads();
#pragma unroll
        for (int j = 0; j < 4; j++) {
            float4 v = *(const float4*)(Ap + k0 + 4 * j);
            float xs[4] = {v.x, v.y, v.z, v.w};
#pragma unroll
            for (int e = 0; e < 4; e++)
                splitf(xs[e], sAhi[ar][ac + 4*j + e], sAlo[ar][ac + 4*j + e]);
        }
#pragma unroll
        for (int j = 0; j < 4; j++) {
            float4 v = *(const float4*)(Wp + (size_t)k0 * 1024 + 4 * j);
            float xs[4] = {v.x, v.y, v.z, v.w};
#pragma unroll
            for (int e = 0; e < 4; e++)
                splitf(xs[e], sWhi[wr][wc + 4*j + e], sWlo[wr][wc + 4*j + e]);
        }
        __syncthreads();

#pragma unroll
        for (int ks = 0; ks < 32; ks += 16) {
            unsigned ahi[2][4], alo[2][4];
#pragma unroll
            for (int mt = 0; mt < 2; mt++) {
                const int r0 = wm0 + mt * 16 + gid;
                const int cc = ks + 2 * qid;
                ahi[mt][0] = *(const unsigned*)&sAhi[r0][cc];
                ahi[mt][1] = *(const unsigned*)&sAhi[r0 + 8][cc];
                ahi[mt][2] = *(const unsigned*)&sAhi[r0][cc + 8];
                ahi[mt][3] = *(const unsigned*)&sAhi[r0 + 8][cc + 8];
                alo[mt][0] = *(const unsigned*)&sAlo[r0][cc];
                alo[mt][1] = *(const unsigned*)&sAlo[r0 + 8][cc];
                alo[mt][2] = *(const unsigned*)&sAlo[r0][cc + 8];
                alo[mt][3] = *(const unsigned*)&sAlo[r0 + 8][cc + 8];
            }
#pragma unroll
            for (int nt = 0; nt < 8; nt++) {
                const int n  = wn0 + nt * 8 + gid;
                const int kk = ks + 2 * qid;
                unsigned bhi[2], blo[2];
                bhi[0] = (unsigned)__bfloat16_as_ushort(sWhi[kk][n])
                       | ((unsigned)__bfloat16_as_ushort(sWhi[kk + 1][n]) << 16);
                bhi[1] = (unsigned)__bfloat16_as_ushort(sWhi[kk + 8][n])
                       | ((unsigned)__bfloat16_as_ushort(sWhi[kk + 9][n]) << 16);
                blo[0] = (unsigned)__bfloat16_as_ushort(sWlo[kk][n])
                       | ((unsigned)__bfloat16_as_ushort(sWlo[kk + 1][n]) << 16);
                blo[1] = (unsigned)__bfloat16_as_ushort(sWlo[kk + 8][n])
                       | ((unsigned)__bfloat16_as_ushort(sWlo[kk + 9][n]) << 16);
#pragma unroll
                for (int mt = 0; mt < 2; mt++) {
                    bf16mma(acc[mt][nt], ahi[mt], bhi);
                    bf16mma(acc[mt][nt], ahi[mt], blo);
                    bf16mma(acc[mt][nt], alo[mt], bhi);
                }
            }
        }
    }

#pragma unroll
    for (int mt = 0; mt < 2; mt++) {
#pragma unroll
        for (int nt = 0; nt < 8; nt++) {
            const int row = crow + wm0 + mt * 16 + gid;
            const int col = ccol + wn0 + nt * 8 + 2 * qid;
            const float b0 = bias[col], b1 = bias[col + 1];
            float2 v0, v1;
            v0.x = acc[mt][nt][0] + b0; v0.y = acc[mt][nt][1] + b1;
            v1.x = acc[mt][nt][2] + b0; v1.y = acc[mt][nt][3] + b1;
            if (MODE == 1) {
                *(float2*)(out + (size_t)row * 1024 + col) = v0;
                *(float2*)(out + (size_t)(row + 8) * 1024 + col) = v1;
            } else {
                const int b = row >> 11, h = col >> 6, d = col & 63;
                const int s = row & 2047;
                float* base = out + ((((size_t)b * Hc + h) * Sc) << 6) + d;
                *(float2*)(base + ((size_t)s << 6)) = v0;
                *(float2*)(base + ((size_t)(s + 8) << 6)) = v1;
            }
        }
    }
}

// ---------------------------------------------------------------------------
// Tensor-core attention. Block = one (b,h) x 64 query rows.
// For each 128-wide key tile: S=QK^T (bf16 split mma), e=exp(s/8) (masked),
// unnormalized e -> attn gmem, e -> smem bf16 split, O_un += E@V (mma).
// End: O = O_un / l, write ctx; store 1/l for norm_kernel.
// ---------------------------------------------------------------------------
#define QST 72
#define KST 72
#define VST 136
#define EST 136
// byte offsets into dynamic smem
#define OFF_QH 0
#define OFF_QL (OFF_QH + 64*QST*2)
#define OFF_KH (OFF_QL + 64*QST*2)
#define OFF_KL (OFF_KH + 128*KST*2)
#define OFF_VH (OFF_KL + 128*KST*2)
#define OFF_VL (OFF_VH + 64*VST*2)
#define OFF_EH (OFF_VL + 64*VST*2)
#define OFF_EL (OFF_EH + 64*EST*2)
#define OFF_SL (OFF_EL + 64*EST*2)
#define OFF_SI (OFF_SL + 64*4)
#define ATTN_SMEM (OFF_SI + 64*4)

__global__ void __launch_bounds__(256, 1) attn_tc(const int* __restrict__ isM,
                                                  float* __restrict__ attn_out)
{
    extern __shared__ char smraw[];
    __nv_bfloat16* qh = (__nv_bfloat16*)(smraw + OFF_QH);
    __nv_bfloat16* ql = (__nv_bfloat16*)(smraw + OFF_QL);
    __nv_bfloat16* kh = (__nv_bfloat16*)(smraw + OFF_KH);
    __nv_bfloat16* kl = (__nv_bfloat16*)(smraw + OFF_KL);
    __nv_bfloat16* vh = (__nv_bfloat16*)(smraw + OFF_VH);  // [d][j] transposed
    __nv_bfloat16* vl = (__nv_bfloat16*)(smraw + OFF_VL);
    __nv_bfloat16* eh = (__nv_bfloat16*)(smraw + OFF_EH);
    __nv_bfloat16* el = (__nv_bfloat16*)(smraw + OFF_EL);
    float* sl   = (float*)(smraw + OFF_SL);
    float* sinv = (float*)(smraw + OFF_SI);

    const int i0 = blockIdx.x * 64;
    const int h  = blockIdx.y;
    const int b  = blockIdx.z;
    const int tid = threadIdx.x;
    const int masked = *isM;

    const int warp = tid >> 5, lane = tid & 31;
    const int mw = warp >> 1, nw = warp & 1;
    const int gid = lane >> 2, qid = lane & 3;

    const size_t bh = (size_t)b * Hc + h;
    const float* Q = g_qh + bh * Sc * Dc;
    const float* K = g_kh + bh * Sc * Dc;
    const float* V = g_vh + bh * Sc * Dc;

    if (tid < 64) sl[tid] = 0.f;

    // load Q tile (64x64) with hi/lo split
#pragma unroll
    for (int t = 0; t < 4; t++) {
        const int idx = tid + t * 256;
        const int row = idx >> 4, d0 = (idx & 15) * 4;
        float4 v = *(const float4*)(Q + (size_t)(i0 + row) * 64 + d0);
        float xs[4] = {v.x, v.y, v.z, v.w};
#pragma unroll
        for (int e = 0; e < 4; e++)
            splitf(xs[e], qh[row*QST + d0 + e], ql[row*QST + d0 + e]);
    }

    int jmax = masked ? (((i0 + 64 + 127) / 128) * 128) : Sc;
    if (jmax > Sc) jmax = Sc;

    float oacc[4][4];
#pragma unroll
    for (int nt = 0; nt < 4; nt++)
#pragma unroll
        for (int e = 0; e < 4; e++) oacc[nt][e] = 0.f;
    float lp0 = 0.f, lp1 = 0.f;

    const int irow0 = i0 + mw * 16 + gid;
    const int irow1 = irow0 + 8;
    const size_t abase0 = (bh * Sc + irow0) * Sc;
    const size_t abase1 = (bh * Sc + irow1) * Sc;

    for (int jt = 0; jt < jmax; jt += 128) {
        __syncthreads();
        // load K tile 128x64 and V tile (transposed) with split
#pragma unroll
        for (int t = 0; t < 8; t++) {
            const int idx = tid + t * 256;
            const int row = idx >> 4, d0 = (idx & 15) * 4;
            float4 kv4 = *(const float4*)(K + (size_t)(jt + row) * 64 + d0);
            float ks4[4] = {kv4.x, kv4.y, kv4.z, kv4.w};
#pragma unroll
            for (int e = 0; e < 4; e++)
                splitf(ks4[e], kh[row*KST + d0 + e], kl[row*KST + d0 + e]);
            float4 vv4 = *(const float4*)(V + (size_t)(jt + row) * 64 + d0);
            float vs4[4] = {vv4.x, vv4.y, vv4.z, vv4.w};
#pragma unroll
            for (int e = 0; e < 4; e++)
                splitf(vs4[e], vh[(d0 + e)*VST + row], vl[(d0 + e)*VST + row]);
        }
        __syncthreads();

        // S = Q K^T for this warp's 16x64 slab
        float sacc[8][4];
#pragma unroll
        for (int nt = 0; nt < 8; nt++)
#pragma unroll
            for (int e = 0; e < 4; e++) sacc[nt][e] = 0.f;

#pragma unroll
        for (int ks = 0; ks < 4; ks++) {
            const int cc = ks * 16 + 2 * qid;
            const int r0 = mw * 16 + gid;
            unsigned ah[4], al[4];
            ah[0] = *(const unsigned*)&qh[r0*QST + cc];
            ah[1] = *(const unsigned*)&qh[(r0+8)*QST + cc];
            ah[2] = *(const unsigned*)&qh[r0*QST + cc + 8];
            ah[3] = *(const unsigned*)&qh[(r0+8)*QST + cc + 8];
            al[0] = *(const unsigned*)&ql[r0*QST + cc];
            al[1] = *(const unsigned*)&ql[(r0+8)*QST + cc];
            al[2] = *(const unsigned*)&ql[r0*QST + cc + 8];
            al[3] = *(const unsigned*)&ql[(r0+8)*QST + cc + 8];
#pragma unroll
            for (int nt = 0; nt < 8; nt++) {
                const int n = nw * 64 + nt * 8 + gid;
                unsigned bh2[2], bl2[2];
                bh2[0] = *(const unsigned*)&kh[n*KST + cc];
                bh2[1] = *(const unsigned*)&kh[n*KST + cc + 8];
                bl2[0] = *(const unsigned*)&kl[n*KST + cc];
                bl2[1] = *(const unsigned*)&kl[n*KST + cc + 8];
                bf16mma(sacc[nt], ah, bh2);
                bf16mma(sacc[nt], ah, bl2);
                bf16mma(sacc[nt], al, bh2);
            }
        }

        // exp, accumulate l, stage E (bf16 split) + write unnormalized attn
        const int lrow0 = mw * 16 + gid;
#pragma unroll
        for (int nt = 0; nt < 8; nt++) {
            const int colt = nw * 64 + nt * 8 + 2 * qid;
            const int j = jt + colt;
            float s00 = sacc[nt][0] * 0.125f, s01 = sacc[nt][1] * 0.125f;
            float s10 = sacc[nt][2] * 0.125f, s11 = sacc[nt][3] * 0.125f;
            if (masked) {
                if (j     > irow0) s00 = -1e9f;
                if (j + 1 > irow0) s01 = -1e9f;
                if (j     > irow1) s10 = -1e9f;
                if (j + 1 > irow1) s11 = -1e9f;
            }
            const float e00 = __expf(s00), e01 = __expf(s01);
            const float e10 = __expf(s10), e11 = __expf(s11);
            lp0 += e00 + e01;
            lp1 += e10 + e11;
            __nv_bfloat16 h0, l0, h1, l1;
            splitf(e00, h0, l0); splitf(e01, h1, l1);
            eh[lrow0*EST + colt] = h0; eh[lrow0*EST + colt + 1] = h1;
            el[lrow0*EST + colt] = l0; el[lrow0*EST + colt + 1] = l1;
            splitf(e10, h0, l0); splitf(e11, h1, l1);
            eh[(lrow0+8)*EST + colt] = h0; eh[(lrow0+8)*EST + colt + 1] = h1;
            el[(lrow0+8)*EST + colt] = l0; el[(lrow0+8)*EST + colt + 1] = l1;
            float2 w0 = {e00, e01}, w1 = {e10, e11};
            *(float2*)(attn_out + abase0 + j) = w0;
            *(float2*)(attn_out + abase1 + j) = w1;
        }
        __syncthreads();

        // O_un += E @ V  (warp slab 16 x 32)
#pragma unroll
        for (int ks = 0; ks < 8; ks++) {
            const int cc = ks * 16 + 2 * qid;
            const int r0 = mw * 16 + gid;
            unsigned ah[4], al[4];
            ah[0] = *(const unsigned*)&eh[r0*EST + cc];
            ah[1] = *(const unsigned*)&eh[(r0+8)*EST + cc];
            ah[2] = *(const unsigned*)&eh[r0*EST + cc + 8];
            ah[3] = *(const unsigned*)&eh[(r0+8)*EST + cc + 8];
            al[0] = *(const unsigned*)&el[r0*EST + cc];
            al[1] = *(const unsigned*)&el[(r0+8)*EST + cc];
            al[2] = *(const unsigned*)&el[r0*EST + cc + 8];
            al[3] = *(const unsigned*)&el[(r0+8)*EST + cc + 8];
#pragma unroll
            for (int nt = 0; nt < 4; nt++) {
                const int n = nw * 32 + nt * 8 + gid;
                unsigned bh2[2], bl2[2];
                bh2[0] = *(const unsigned*)&vh[n*VST + cc];
                bh2[1] = *(const unsigned*)&vh[n*VST + cc + 8];
                bl2[0] = *(const unsigned*)&vl[n*VST + cc];
                bl2[1] = *(const unsigned*)&vl[n*VST + cc + 8];
                bf16mma(oacc[nt], ah, bh2);
                bf16mma(oacc[nt], ah, bl2);
                bf16mma(oacc[nt], al, bh2);
            }
        }
    }

    // reduce row sums over quad, then across warp-cols via smem atomics
    lp0 += __shfl_xor_sync(0xffffffffu, lp0, 1);
    lp0 += __shfl_xor_sync(0xffffffffu, lp0, 2);
    lp1 += __shfl_xor_sync(0xffffffffu, lp1, 1);
    lp1 += __shfl_xor_sync(0xffffffffu, lp1, 2);
    if (qid == 0) {
        atomicAdd(&sl[mw*16 + gid], lp0);
        atomicAdd(&sl[mw*16 + gid + 8], lp1);
    }
    __syncthreads();
    if (tid < 64) {
        const float inv = 1.f / sl[tid];
        sinv[tid] = inv;
        g_l[bh * Sc + i0 + tid] = inv;
    }
    __syncthreads();

    const float iv0 = sinv[mw*16 + gid];
    const float iv1 = sinv[mw*16 + gid + 8];
    float* ctx = g_ctx + ((size_t)b * Sc) * Ec + (size_t)h * Dc;
#pragma unroll
    for (int nt = 0; nt < 4; nt++) {
        const int col = nw * 32 + nt * 8 + 2 * qid;
        float2 v0 = {oacc[nt][0] * iv0, oacc[nt][1] * iv0};
        float2 v1 = {oacc[nt][2] * iv1, oacc[nt][3] * iv1};
        *(float2*)(ctx + (size_t)(irow0) * Ec + col) = v0;
        *(float2*)(ctx + (size_t)(irow1) * Ec + col) = v1;
    }
}

// ---------------------------------------------------------------------------
// Normalize attn rows by 1/l and zero-fill masked tail. One block per row.
// ---------------------------------------------------------------------------
__global__ void __launch_bounds__(256) norm_kernel(const int* __restrict__ isM,
                                                   float* __restrict__ attn)
{
    const int r = blockIdx.x;                   // bh*Sc + i
    const int i = r & (Sc - 1);
    const int masked = *isM;
    const int limit = masked ? (i + 1) : Sc;
    const float inv = g_l[r];
    float* row = attn + (size_t)r * Sc;

#pragma unroll
    for (int t = 0; t < 2; t++) {
        const int j = (threadIdx.x + t * 256) * 4;
        if (j + 4 <= limit) {
            float4 v = *(float4*)(row + j);
            v.x *= inv; v.y *= inv; v.z *= inv; v.w *= inv;
            *(float4*)(row + j) = v;
        } else if (j >= limit) {
            float4 z = {0.f, 0.f, 0.f, 0.f};
            *(float4*)(row + j) = z;
        } else {
            float4 v = *(float4*)(row + j);
            v.x = (j     < limit) ? v.x * inv : 0.f;
            v.y = (j + 1 < limit) ? v.y * inv : 0.f;
            v.z = (j + 2 < limit) ? v.z * inv : 0.f;
            v.w = (j + 3 < limit) ? v.w * inv : 0.f;
            *(float4*)(row + j) = v;
        }
    }
}

// ---------------------------------------------------------------------------
// Residual + LayerNorm (unchanged)
// ---------------------------------------------------------------------------
__global__ void __launch_bounds__(256) ln_kernel(const float* __restrict__ qin,
                                                 float* __restrict__ out)
{
    const size_t row = blockIdx.x;
    const int tid = threadIdx.x;
    float4 x  = *(const float4*)(g_tmp + row * 1024 + tid * 4);
    float4 qq = *(const float4*)(qin   + row * 1024 + tid * 4);
    x.x += qq.x; x.y += qq.y; x.z += qq.z; x.w += qq.w;

    float s  = x.x + x.y + x.z + x.w;
    float s2 = x.x*x.x + x.y*x.y + x.z*x.z + x.w*x.w;

    __shared__ float rs[8], rs2[8];
    const int w = tid >> 5, lane = tid & 31;
#pragma unroll
    for (int o = 16; o; o >>= 1) {
        s  += __shfl_xor_sync(0xffffffffu, s,  o);
        s2 += __shfl_xor_sync(0xffffffffu, s2, o);
    }
    if (!lane) { rs[w] = s; rs2[w] = s2; }
    __syncthreads();
    if (w == 0) {
        float a  = (lane < 8) ? rs[lane]  : 0.f;
        float a2 = (lane < 8) ? rs2[lane] : 0.f;
#pragma unroll
        for (int o = 4; o; o >>= 1) {
            a  += __shfl_xor_sync(0xffffffffu, a,  o);
            a2 += __shfl_xor_sync(0xffffffffu, a2, o);
        }
        if (!lane) { rs[0] = a; rs2[0] = a2; }
    }
    __syncthreads();
    const float mu   = rs[0] * (1.f / 1024.f);
    const float var  = rs2[0] * (1.f / 1024.f) - mu * mu;
    const float rstd = rsqrtf(var + 1e-5f);
    float4 o;
    o.x = (x.x - mu) * rstd; o.y = (x.y - mu) * rstd;
    o.z = (x.z - mu) * rstd; o.w = (x.w - mu) * rstd;
    *(float4*)(out + row * 1024 + tid * 4) = o;
}

// ---------------------------------------------------------------------------
extern "C" void kernel_launch(void* const* d_in, const int* in_sizes, int n_in,
                              void* d_out, int out_size)
{
    (void)in_sizes; (void)n_in; (void)out_size;
    const float* q  = (const float*)d_in[0];
    const float* k  = (const float*)d_in[1];
    const float* v  = (const float*)d_in[2];
    const float* Wq = (const float*)d_in[3];
    const float* bq = (const float*)d_in[4];
    const float* Wk = (const float*)d_in[5];
    const float* bk = (const float*)d_in[6];
    const float* Wv = (const float*)d_in[7];
    const float* bv = (const float*)d_in[8];
    const float* Wo = (const float*)d_in[9];
    const float* bo = (const float*)d_in[10];
    const int*   isM = (const int*)d_in[11];

    float* out  = (float*)d_out;
    float* attn = out + (size_t)Bc * Sc * Ec;

    cudaFuncSetAttribute(attn_tc,
                         cudaFuncAttributeMaxDynamicSharedMemorySize, ATTN_SMEM);

    dim3 gg(Ec / 128, M_TOT / 128);
    gemm_tc<0><<<gg, 256>>>(q, Wq, bq, 0);
    gemm_tc<0><<<gg, 256>>>(k, Wk, bk, 1);
    gemm_tc<0><<<gg, 256>>>(v, Wv, bv, 2);

    attn_tc<<<dim3(Sc / 64, Hc, Bc), 256, ATTN_SMEM>>>(isM, attn);
    norm_kernel<<<Bc * Hc * Sc, 256>>>(isM, attn);

    gemm_tc<1><<<gg, 256>>>(nullptr, Wo, bo, 3);
    ln_kernel<<<M_TOT, 256>>>(q, out);
}

// round 4
// speedup vs baseline: 2.6138x; 1.0742x over previous
#include <cuda_runtime.h>
#include <cuda_bf16.h>
#include <cstddef>

// Problem constants
#define Bc 2
#define Sc 2048
#define Ec 1024
#define Hc 16
#define Dc 64
#define M_TOT (Bc*Sc)

// Scratch (device globals)
__device__ float g_qh[(size_t)Bc*Hc*Sc*Dc];   // [b,h,s,d]
__device__ float g_kh[(size_t)Bc*Hc*Sc*Dc];
__device__ float g_vh[(size_t)Bc*Hc*Sc*Dc];
__device__ float g_ctx[(size_t)Bc*Sc*Ec];     // [b,s,h*d]
__device__ float g_tmp[(size_t)Bc*Sc*Ec];     // pre-LN output
__device__ float g_l[(size_t)Bc*Hc*Sc];       // per-row 1/sum

__device__ __forceinline__ void bf16mma(float c[4], const unsigned a[4],
                                        unsigned b0, unsigned b1)
{
    asm volatile(
        "mma.sync.aligned.m16n8k16.row.col.f32.bf16.bf16.f32 "
        "{%0,%1,%2,%3}, {%4,%5,%6,%7}, {%8,%9}, {%0,%1,%2,%3};\n"
        : "+f"(c[0]), "+f"(c[1]), "+f"(c[2]), "+f"(c[3])
        : "r"(a[0]), "r"(a[1]), "r"(a[2]), "r"(a[3]), "r"(b0), "r"(b1));
}

__device__ __forceinline__ void bf16mma4(float c[4], const unsigned a[4],
                                         const unsigned b[2])
{
    bf16mma(c, a, b[0], b[1]);
}

__device__ __forceinline__ void splitf(float x, __nv_bfloat16& h, __nv_bfloat16& l)
{
    h = __float2bfloat16(x);
    l = __float2bfloat16(x - __bfloat162float(h));
}

// pack two floats into bf16x2 hi and residual lo words
__device__ __forceinline__ void split2pack(float a, float b, unsigned& hi, unsigned& lo)
{
    __nv_bfloat16 ha = __float2bfloat16(a), hb = __float2bfloat16(b);
    __nv_bfloat16 la = __float2bfloat16(a - __bfloat162float(ha));
    __nv_bfloat16 lb = __float2bfloat16(b - __bfloat162float(hb));
    hi = (unsigned)__bfloat16_as_ushort(ha) | ((unsigned)__bfloat16_as_ushort(hb) << 16);
    lo = (unsigned)__bfloat16_as_ushort(la) | ((unsigned)__bfloat16_as_ushort(lb) << 16);
}

__device__ __forceinline__ void ldmx4(unsigned addr, unsigned r[4])
{
    asm volatile("ldmatrix.sync.aligned.m8n8.x4.shared.b16 {%0,%1,%2,%3}, [%4];"
                 : "=r"(r[0]), "=r"(r[1]), "=r"(r[2]), "=r"(r[3]) : "r"(addr));
}

__device__ __forceinline__ void ldmx4t(unsigned addr, unsigned r[4])
{
    asm volatile("ldmatrix.sync.aligned.m8n8.x4.trans.shared.b16 {%0,%1,%2,%3}, [%4];"
                 : "=r"(r[0]), "=r"(r[1]), "=r"(r[2]), "=r"(r[3]) : "r"(addr));
}

// ---------------------------------------------------------------------------
// Tensor-core projection GEMM (unchanged — known good)
// ---------------------------------------------------------------------------
template<int MODE>
__global__ void __launch_bounds__(256) gemm_tc(const float* __restrict__ Ain,
                                               const float* __restrict__ W,
                                               const float* __restrict__ bias,
                                               int outsel)
{
    const float* A = Ain ? Ain : g_ctx;
    float* out = (outsel == 0) ? g_qh : (outsel == 1) ? g_kh
               : (outsel == 2) ? g_vh : g_tmp;

    __shared__ __align__(16) __nv_bfloat16 sAhi[128][40];
    __shared__ __align__(16) __nv_bfloat16 sAlo[128][40];
    __shared__ __align__(16) __nv_bfloat16 sWhi[32][136];
    __shared__ __align__(16) __nv_bfloat16 sWlo[32][136];

    const int tid  = threadIdx.x;
    const int crow = blockIdx.y * 128;
    const int ccol = blockIdx.x * 128;

    const int warp = tid >> 5, lane = tid & 31;
    const int wm0 = (warp >> 1) * 32;
    const int wn0 = (warp & 1) * 64;
    const int gid = lane >> 2;
    const int qid = lane & 3;

    const int ar = tid >> 1;
    const int ac = (tid & 1) * 16;
    const int wr = tid >> 3;
    const int wc = (tid & 7) * 16;

    const float* Ap = A + (size_t)(crow + ar) * 1024 + ac;
    const float* Wp = W + (size_t)wr * 1024 + ccol + wc;

    float acc[2][8][4];
#pragma unroll
    for (int mt = 0; mt < 2; mt++)
#pragma unroll
        for (int nt = 0; nt < 8; nt++)
#pragma unroll
            for (int e = 0; e < 4; e++) acc[mt][nt][e] = 0.f;

    for (int k0 = 0; k0 < 1024; k0 += 32) {
        __syncthreads();
#pragma unroll
        for (int j = 0; j < 4; j++) {
            float4 v = *(const float4*)(Ap + k0 + 4 * j);
            float xs[4] = {v.x, v.y, v.z, v.w};
#pragma unroll
            for (int e = 0; e < 4; e++)
                splitf(xs[e], sAhi[ar][ac + 4*j + e], sAlo[ar][ac + 4*j + e]);
        }
#pragma unroll
        for (int j = 0; j < 4; j++) {
            float4 v = *(const float4*)(Wp + (size_t)k0 * 1024 + 4 * j);
            float xs[4] = {v.x, v.y, v.z, v.w};
#pragma unroll
            for (int e = 0; e < 4; e++)
                splitf(xs[e], sWhi[wr][wc + 4*j + e], sWlo[wr][wc + 4*j + e]);
        }
        __syncthreads();

#pragma unroll
        for (int ks = 0; ks < 32; ks += 16) {
            unsigned ahi[2][4], alo[2][4];
#pragma unroll
            for (int mt = 0; mt < 2; mt++) {
                const int r0 = wm0 + mt * 16 + gid;
                const int cc = ks + 2 * qid;
                ahi[mt][0] = *(const unsigned*)&sAhi[r0][cc];
                ahi[mt][1] = *(const unsigned*)&sAhi[r0 + 8][cc];
                ahi[mt][2] = *(const unsigned*)&sAhi[r0][cc + 8];
                ahi[mt][3] = *(const unsigned*)&sAhi[r0 + 8][cc + 8];
                alo[mt][0] = *(const unsigned*)&sAlo[r0][cc];
                alo[mt][1] = *(const unsigned*)&sAlo[r0 + 8][cc];
                alo[mt][2] = *(const unsigned*)&sAlo[r0][cc + 8];
                alo[mt][3] = *(const unsigned*)&sAlo[r0 + 8][cc + 8];
            }
#pragma unroll
            for (int nt = 0; nt < 8; nt++) {
                const int n  = wn0 + nt * 8 + gid;
                const int kk = ks + 2 * qid;
                unsigned bhi[2], blo[2];
                bhi[0] = (unsigned)__bfloat16_as_ushort(sWhi[kk][n])
                       | ((unsigned)__bfloat16_as_ushort(sWhi[kk + 1][n]) << 16);
                bhi[1] = (unsigned)__bfloat16_as_ushort(sWhi[kk + 8][n])
                       | ((unsigned)__bfloat16_as_ushort(sWhi[kk + 9][n]) << 16);
                blo[0] = (unsigned)__bfloat16_as_ushort(sWlo[kk][n])
                       | ((unsigned)__bfloat16_as_ushort(sWlo[kk + 1][n]) << 16);
                blo[1] = (unsigned)__bfloat16_as_ushort(sWlo[kk + 8][n])
                       | ((unsigned)__bfloat16_as_ushort(sWlo[kk + 9][n]) << 16);
#pragma unroll
                for (int mt = 0; mt < 2; mt++) {
                    bf16mma4(acc[mt][nt], ahi[mt], bhi);
                    bf16mma4(acc[mt][nt], ahi[mt], blo);
                    bf16mma4(acc[mt][nt], alo[mt], bhi);
                }
            }
        }
    }

#pragma unroll
    for (int mt = 0; mt < 2; mt++) {
#pragma unroll
        for (int nt = 0; nt < 8; nt++) {
            const int row = crow + wm0 + mt * 16 + gid;
            const int col = ccol + wn0 + nt * 8 + 2 * qid;
            const float b0 = bias[col], b1 = bias[col + 1];
            float2 v0, v1;
            v0.x = acc[mt][nt][0] + b0; v0.y = acc[mt][nt][1] + b1;
            v1.x = acc[mt][nt][2] + b0; v1.y = acc[mt][nt][3] + b1;
            if (MODE == 1) {
                *(float2*)(out + (size_t)row * 1024 + col) = v0;
                *(float2*)(out + (size_t)(row + 8) * 1024 + col) = v1;
            } else {
                const int b = row >> 11, h = col >> 6, d = col & 63;
                const int s = row & 2047;
                float* base = out + ((((size_t)b * Hc + h) * Sc) << 6) + d;
                *(float2*)(base + ((size_t)s << 6)) = v0;
                *(float2*)(base + ((size_t)(s + 8) << 6)) = v1;
            }
        }
    }
}

// ---------------------------------------------------------------------------
// Tensor-core attention v2. Block = one (b,h) x 256 query rows, 8 warps,
// warp owns 32 rows (2 m-tiles). Full-width S in registers -> exp in regs ->
// E@V directly from register A-fragments (no E smem). Q/K/V smem, fragments
// via ldmatrix (V via .trans from row-major tile).
// ---------------------------------------------------------------------------
#define QST 72   // shared stride (bf16 elems) for Q/K/V tiles
#define OFF_QH 0
#define OFF_QL (OFF_QH + 256*QST*2)
#define OFF_KH (OFF_QL + 256*QST*2)
#define OFF_KL (OFF_KH + 128*QST*2)
#define OFF_VH (OFF_KL + 128*QST*2)
#define OFF_VL (OFF_VH + 128*QST*2)
#define ATTN_SMEM (OFF_VL + 128*QST*2)

__global__ void __launch_bounds__(256, 1) attn_tc(const int* __restrict__ isM,
                                                  float* __restrict__ attn_out)
{
    extern __shared__ char smraw[];
    __nv_bfloat16* qh = (__nv_bfloat16*)(smraw + OFF_QH);
    __nv_bfloat16* ql = (__nv_bfloat16*)(smraw + OFF_QL);
    __nv_bfloat16* kh = (__nv_bfloat16*)(smraw + OFF_KH);
    __nv_bfloat16* kl = (__nv_bfloat16*)(smraw + OFF_KL);
    __nv_bfloat16* vh = (__nv_bfloat16*)(smraw + OFF_VH);
    __nv_bfloat16* vl = (__nv_bfloat16*)(smraw + OFF_VL);

    const int i0  = blockIdx.x * 256;
    const int h   = blockIdx.y;
    const int b   = blockIdx.z;
    const int tid = threadIdx.x;
    const int masked = *isM;

    const int warp = tid >> 5, lane = tid & 31;
    const int gid = lane >> 2, qid = lane & 3;
    const int grp = lane >> 3, li = lane & 7;

    const size_t bh = (size_t)b * Hc + h;
    const float* Q = g_qh + bh * Sc * Dc;
    const float* K = g_kh + bh * Sc * Dc;
    const float* V = g_vh + bh * Sc * Dc;

    const unsigned qh_s = (unsigned)__cvta_generic_to_shared(qh);
    const unsigned ql_s = (unsigned)__cvta_generic_to_shared(ql);
    const unsigned kh_s = (unsigned)__cvta_generic_to_shared(kh);
    const unsigned kl_s = (unsigned)__cvta_generic_to_shared(kl);
    const unsigned vh_s = (unsigned)__cvta_generic_to_shared(vh);
    const unsigned vl_s = (unsigned)__cvta_generic_to_shared(vl);

    // ldmatrix per-lane byte offsets
    const unsigned offA  = ((li + ((grp & 1) << 3)) * QST + ((grp >> 1) << 3)) * 2; // A / V-trans pattern
    const unsigned offBK = ((li + ((grp & 2) << 2)) * QST + ((grp & 1) << 3)) * 2;  // K B pattern

    // ---- load Q tile 256x64 (hi/lo packed) ----
#pragma unroll
    for (int t = 0; t < 16; t++) {
        const int idx = tid + t * 256;
        const int row = idx >> 4, d0 = (idx & 15) * 4;
        float4 v = *(const float4*)(Q + (size_t)(i0 + row) * 64 + d0);
        unsigned h01, l01, h23, l23;
        split2pack(v.x, v.y, h01, l01);
        split2pack(v.z, v.w, h23, l23);
        *(unsigned*)&qh[row * QST + d0]     = h01;
        *(unsigned*)&ql[row * QST + d0]     = l01;
        *(unsigned*)&qh[row * QST + d0 + 2] = h23;
        *(unsigned*)&ql[row * QST + d0 + 2] = l23;
    }

    int jmax = masked ? (i0 + 256) : Sc;
    if (jmax > Sc) jmax = Sc;

    float oacc[2][8][4];
#pragma unroll
    for (int mt = 0; mt < 2; mt++)
#pragma unroll
        for (int nt = 0; nt < 8; nt++)
#pragma unroll
            for (int e = 0; e < 4; e++) oacc[mt][nt][e] = 0.f;
    float lpa[4] = {0.f, 0.f, 0.f, 0.f};   // [mt*2 + rr] row sums

    const int r0w = i0 + warp * 32;

    for (int jt = 0; jt < jmax; jt += 128) {
        __syncthreads();
        // ---- load K, V tiles 128x64 each (both row-major, packed) ----
#pragma unroll
        for (int t = 0; t < 8; t++) {
            const int idx = tid + t * 256;
            const int row = idx >> 4, d0 = (idx & 15) * 4;
            float4 kv = *(const float4*)(K + (size_t)(jt + row) * 64 + d0);
            unsigned h01, l01, h23, l23;
            split2pack(kv.x, kv.y, h01, l01);
            split2pack(kv.z, kv.w, h23, l23);
            *(unsigned*)&kh[row * QST + d0]     = h01;
            *(unsigned*)&kl[row * QST + d0]     = l01;
            *(unsigned*)&kh[row * QST + d0 + 2] = h23;
            *(unsigned*)&kl[row * QST + d0 + 2] = l23;
            float4 vv = *(const float4*)(V + (size_t)(jt + row) * 64 + d0);
            split2pack(vv.x, vv.y, h01, l01);
            split2pack(vv.z, vv.w, h23, l23);
            *(unsigned*)&vh[row * QST + d0]     = h01;
            *(unsigned*)&vl[row * QST + d0]     = l01;
            *(unsigned*)&vh[row * QST + d0 + 2] = h23;
            *(unsigned*)&vl[row * QST + d0 + 2] = l23;
        }
        __syncthreads();

#pragma unroll
        for (int half = 0; half < 2; half++) {
            // ---- S = Q K^T for 32 rows x 64 cols ----
            float sacc[2][8][4];
#pragma unroll
            for (int mt = 0; mt < 2; mt++)
#pragma unroll
                for (int nt = 0; nt < 8; nt++)
#pragma unroll
                    for (int e = 0; e < 4; e++) sacc[mt][nt][e] = 0.f;

#pragma unroll
            for (int ks = 0; ks < 4; ks++) {
                unsigned qaH[2][4], qaL[2][4];
#pragma unroll
                for (int mt = 0; mt < 2; mt++) {
                    const unsigned qoff = (unsigned)((warp*32 + mt*16) * QST * 2 + ks * 32) + offA;
                    ldmx4(qh_s + qoff, qaH[mt]);
                    ldmx4(ql_s + qoff, qaL[mt]);
                }
#pragma unroll
                for (int ntp = 0; ntp < 4; ntp++) {
                    unsigned kbH[4], kbL[4];
                    const unsigned koff = (unsigned)((half*64 + ntp*16) * QST * 2 + ks * 32) + offBK;
                    ldmx4(kh_s + koff, kbH);
                    ldmx4(kl_s + koff, kbL);
#pragma unroll
                    for (int mt = 0; mt < 2; mt++) {
                        bf16mma(sacc[mt][2*ntp],   qaH[mt], kbH[0], kbH[1]);
                        bf16mma(sacc[mt][2*ntp],   qaH[mt], kbL[0], kbL[1]);
                        bf16mma(sacc[mt][2*ntp],   qaL[mt], kbH[0], kbH[1]);
                        bf16mma(sacc[mt][2*ntp+1], qaH[mt], kbH[2], kbH[3]);
                        bf16mma(sacc[mt][2*ntp+1], qaH[mt], kbL[2], kbL[3]);
                        bf16mma(sacc[mt][2*ntp+1], qaL[mt], kbH[2], kbH[3]);
                    }
                }
            }

            // ---- exp + attn write + E@V ----
#pragma unroll
            for (int kc2 = 0; kc2 < 4; kc2++) {
                unsigned aEh[2][4], aEl[2][4];
#pragma unroll
                for (int mt = 0; mt < 2; mt++) {
                    const int row0 = r0w + mt*16 + gid;
                    const int row1 = row0 + 8;
                    const int jc = jt + half*64 + kc2*16 + 2*qid;
                    const int t0 = 2*kc2, t1 = 2*kc2 + 1;
                    float s00 = sacc[mt][t0][0] * 0.125f;
                    float s01 = sacc[mt][t0][1] * 0.125f;
                    float s10 = sacc[mt][t0][2] * 0.125f;
                    float s11 = sacc[mt][t0][3] * 0.125f;
                    float s02 = sacc[mt][t1][0] * 0.125f;
                    float s03 = sacc[mt][t1][1] * 0.125f;
                    float s12 = sacc[mt][t1][2] * 0.125f;
                    float s13 = sacc[mt][t1][3] * 0.125f;
                    if (masked) {
                        if (jc     > row0) s00 = -1e9f;
                        if (jc + 1 > row0) s01 = -1e9f;
                        if (jc + 8 > row0) s02 = -1e9f;
                        if (jc + 9 > row0) s03 = -1e9f;
                        if (jc     > row1) s10 = -1e9f;
                        if (jc + 1 > row1) s11 = -1e9f;
                        if (jc + 8 > row1) s12 = -1e9f;
                        if (jc + 9 > row1) s13 = -1e9f;
                    }
                    const float e00 = __expf(s00), e01 = __expf(s01);
                    const float e02 = __expf(s02), e03 = __expf(s03);
                    const float e10 = __expf(s10), e11 = __expf(s11);
                    const float e12 = __expf(s12), e13 = __expf(s13);
                    lpa[mt*2]     += e00 + e01 + e02 + e03;
                    lpa[mt*2 + 1] += e10 + e11 + e12 + e13;
                    const size_t a0 = (bh * Sc + row0) * Sc;
                    const size_t a1 = (bh * Sc + row1) * Sc;
                    float2 w;
                    w.x = e00; w.y = e01; *(float2*)(attn_out + a0 + jc)     = w;
                    w.x = e02; w.y = e03; *(float2*)(attn_out + a0 + jc + 8) = w;
                    w.x = e10; w.y = e11; *(float2*)(attn_out + a1 + jc)     = w;
                    w.x = e12; w.y = e13; *(float2*)(attn_out + a1 + jc + 8) = w;
                    split2pack(e00, e01, aEh[mt][0], aEl[mt][0]);
                    split2pack(e10, e11, aEh[mt][1], aEl[mt][1]);
                    split2pack(e02, e03, aEh[mt][2], aEl[mt][2]);
                    split2pack(e12, e13, aEh[mt][3], aEl[mt][3]);
                }
#pragma unroll
                for (int ntp = 0; ntp < 4; ntp++) {
                    unsigned vbH[4], vbL[4];
                    const unsigned voff = (unsigned)((half*64 + kc2*16) * QST * 2 + ntp * 32) + offA;
                    ldmx4t(vh_s + voff, vbH);
                    ldmx4t(vl_s + voff, vbL);
#pragma unroll
                    for (int mt = 0; mt < 2; mt++) {
                        bf16mma(oacc[mt][2*ntp],   aEh[mt], vbH[0], vbH[1]);
                        bf16mma(oacc[mt][2*ntp],   aEh[mt], vbL[0], vbL[1]);
                        bf16mma(oacc[mt][2*ntp],   aEl[mt], vbH[0], vbH[1]);
                        bf16mma(oacc[mt][2*ntp+1], aEh[mt], vbH[2], vbH[3]);
                        bf16mma(oacc[mt][2*ntp+1], aEh[mt], vbL[2], vbL[3]);
                        bf16mma(oacc[mt][2*ntp+1], aEl[mt], vbH[2], vbH[3]);
                    }
                }
            }
        }
    }

    // ---- finalize: row sums are warp-local (quad reduce), scale, write ----
    float inv[4];
#pragma unroll
    for (int r = 0; r < 4; r++) {
        float s = lpa[r];
        s += __shfl_xor_sync(0xffffffffu, s, 1);
        s += __shfl_xor_sync(0xffffffffu, s, 2);
        inv[r] = 1.f / s;
    }
    if (qid == 0) {
#pragma unroll
        for (int mt = 0; mt < 2; mt++) {
            g_l[bh * Sc + r0w + mt*16 + gid]     = inv[mt*2];
            g_l[bh * Sc + r0w + mt*16 + gid + 8] = inv[mt*2 + 1];
        }
    }

    float* ctx = g_ctx + ((size_t)b * Sc) * Ec + (size_t)h * Dc;
#pragma unroll
    for (int mt = 0; mt < 2; mt++) {
        const int row0 = r0w + mt*16 + gid;
        const int row1 = row0 + 8;
        const float iv0 = inv[mt*2], iv1 = inv[mt*2 + 1];
#pragma unroll
        for (int nt = 0; nt < 8; nt++) {
            const int col = nt * 8 + 2 * qid;
            float2 v0, v1;
            v0.x = oacc[mt][nt][0] * iv0; v0.y = oacc[mt][nt][1] * iv0;
            v1.x = oacc[mt][nt][2] * iv1; v1.y = oacc[mt][nt][3] * iv1;
            *(float2*)(ctx + (size_t)row0 * Ec + col) = v0;
            *(float2*)(ctx + (size_t)row1 * Ec + col) = v1;
        }
    }
}

// ---------------------------------------------------------------------------
// Normalize attn rows by 1/l, zero-fill masked tail. One block per row.
// ---------------------------------------------------------------------------
__global__ void __launch_bounds__(256) norm_kernel(const int* __restrict__ isM,
                                                   float* __restrict__ attn)
{
    const int r = blockIdx.x;
    const int i = r & (Sc - 1);
    const int masked = *isM;
    const int limit = masked ? (i + 1) : Sc;
    const float inv = g_l[r];
    float* row = attn + (size_t)r * Sc;

#pragma unroll
    for (int t = 0; t < 2; t++) {
        const int j = (threadIdx.x + t * 256) * 4;
        if (j + 4 <= limit) {
            float4 v = *(float4*)(row + j);
            v.x *= inv; v.y *= inv; v.z *= inv; v.w *= inv;
            *(float4*)(row + j) = v;
        } else if (j >= limit) {
            float4 z = {0.f, 0.f, 0.f, 0.f};
            *(float4*)(row + j) = z;
        } else {
            float4 v = *(float4*)(row + j);
            v.x = (j     < limit) ? v.x * inv : 0.f;
            v.y = (j + 1 < limit) ? v.y * inv : 0.f;
            v.z = (j + 2 < limit) ? v.z * inv : 0.f;
            v.w = (j + 3 < limit) ? v.w * inv : 0.f;
            *(float4*)(row + j) = v;
        }
    }
}

// ---------------------------------------------------------------------------
// Residual + LayerNorm (unchanged)
// ---------------------------------------------------------------------------
__global__ void __launch_bounds__(256) ln_kernel(const float* __restrict__ qin,
                                                 float* __restrict__ out)
{
    const size_t row = blockIdx.x;
    const int tid = threadIdx.x;
    float4 x  = *(const float4*)(g_tmp + row * 1024 + tid * 4);
    float4 qq = *(const float4*)(qin   + row * 1024 + tid * 4);
    x.x += qq.x; x.y += qq.y; x.z += qq.z; x.w += qq.w;

    float s  = x.x + x.y + x.z + x.w;
    float s2 = x.x*x.x + x.y*x.y + x.z*x.z + x.w*x.w;

    __shared__ float rs[8], rs2[8];
    const int w = tid >> 5, lane = tid & 31;
#pragma unroll
    for (int o = 16; o; o >>= 1) {
        s  += __shfl_xor_sync(0xffffffffu, s,  o);
        s2 += __shfl_xor_sync(0xffffffffu, s2, o);
    }
    if (!lane) { rs[w] = s; rs2[w] = s2; }
    __syncthreads();
    if (w == 0) {
        float a  = (lane < 8) ? rs[lane]  : 0.f;
        float a2 = (lane < 8) ? rs2[lane] : 0.f;
#pragma unroll
        for (int o = 4; o; o >>= 1) {
            a  += __shfl_xor_sync(0xffffffffu, a,  o);
            a2 += __shfl_xor_sync(0xffffffffu, a2, o);
        }
        if (!lane) { rs[0] = a; rs2[0] = a2; }
    }
    __syncthreads();
    const float mu   = rs[0] * (1.f / 1024.f);
    const float var  = rs2[0] * (1.f / 1024.f) - mu * mu;
    const float rstd = rsqrtf(var + 1e-5f);
    float4 o;
    o.x = (x.x - mu) * rstd; o.y = (x.y - mu) * rstd;
    o.z = (x.z - mu) * rstd; o.w = (x.w - mu) * rstd;
    *(float4*)(out + row * 1024 + tid * 4) = o;
}

// ---------------------------------------------------------------------------
extern "C" void kernel_launch(void* const* d_in, const int* in_sizes, int n_in,
                              void* d_out, int out_size)
{
    (void)in_sizes; (void)n_in; (void)out_size;
    const float* q  = (const float*)d_in[0];
    const float* k  = (const float*)d_in[1];
    const float* v  = (const float*)d_in[2];
    const float* Wq = (const float*)d_in[3];
    const float* bq = (const float*)d_in[4];
    const float* Wk = (const float*)d_in[5];
    const float* bk = (const float*)d_in[6];
    const float* Wv = (const float*)d_in[7];
    const float* bv = (const float*)d_in[8];
    const float* Wo = (const float*)d_in[9];
    const float* bo = (const float*)d_in[10];
    const int*   isM = (const int*)d_in[11];

    float* out  = (float*)d_out;
    float* attn = out + (size_t)Bc * Sc * Ec;

    cudaFuncSetAttribute(attn_tc,
                         cudaFuncAttributeMaxDynamicSharedMemorySize, ATTN_SMEM);

    dim3 gg(Ec / 128, M_TOT / 128);
    gemm_tc<0><<<gg, 256>>>(q, Wq, bq, 0);
    gemm_tc<0><<<gg, 256>>>(k, Wk, bk, 1);
    gemm_tc<0><<<gg, 256>>>(v, Wv, bv, 2);

    attn_tc<<<dim3(Sc / 256, Hc, Bc), 256, ATTN_SMEM>>>(isM, attn);
    norm_kernel<<<Bc * Hc * Sc, 256>>>(isM, attn);

    gemm_tc<1><<<gg, 256>>>(nullptr, Wo, bo, 3);
    ln_kernel<<<M_TOT, 256>>>(q, out);
}

// round 5
// speedup vs baseline: 2.7690x; 1.0594x over previous
#include <cuda_runtime.h>
#include <cuda_bf16.h>
#include <cstddef>

// Problem constants
#define Bc 2
#define Sc 2048
#define Ec 1024
#define Hc 16
#define Dc 64
#define M_TOT (Bc*Sc)

// Scratch (device globals)
__device__ float g_qh[(size_t)Bc*Hc*Sc*Dc];   // [b,h,s,d] (tf32-rounded fp32)
__device__ float g_kh[(size_t)Bc*Hc*Sc*Dc];
__device__ float g_vh[(size_t)Bc*Hc*Sc*Dc];
__device__ float g_ctx[(size_t)Bc*Sc*Ec];     // [b,s,h*d]
__device__ float g_tmp[(size_t)Bc*Sc*Ec];     // pre-LN output

// ---------------- helpers ----------------
__device__ __forceinline__ void bf16mma(float c[4], const unsigned a[4],
                                        unsigned b0, unsigned b1)
{
    asm volatile(
        "mma.sync.aligned.m16n8k16.row.col.f32.bf16.bf16.f32 "
        "{%0,%1,%2,%3}, {%4,%5,%6,%7}, {%8,%9}, {%0,%1,%2,%3};\n"
        : "+f"(c[0]), "+f"(c[1]), "+f"(c[2]), "+f"(c[3])
        : "r"(a[0]), "r"(a[1]), "r"(a[2]), "r"(a[3]), "r"(b0), "r"(b1));
}

__device__ __forceinline__ void tf32mma(float c[4], const unsigned a[4],
                                        unsigned b0, unsigned b1)
{
    asm volatile(
        "mma.sync.aligned.m16n8k8.row.col.f32.tf32.tf32.f32 "
        "{%0,%1,%2,%3}, {%4,%5,%6,%7}, {%8,%9}, {%0,%1,%2,%3};\n"
        : "+f"(c[0]), "+f"(c[1]), "+f"(c[2]), "+f"(c[3])
        : "r"(a[0]), "r"(a[1]), "r"(a[2]), "r"(a[3]), "r"(b0), "r"(b1));
}

__device__ __forceinline__ unsigned cvt_tf32(float x)
{
    unsigned r;
    asm("cvt.rna.tf32.f32 %0, %1;" : "=r"(r) : "f"(x));
    return r;
}

__device__ __forceinline__ void splitf(float x, __nv_bfloat16& h, __nv_bfloat16& l)
{
    h = __float2bfloat16(x);
    l = __float2bfloat16(x - __bfloat162float(h));
}

__device__ __forceinline__ void cpasync16(unsigned s, const void* g)
{
    asm volatile("cp.async.cg.shared.global [%0], [%1], 16;\n" :: "r"(s), "l"(g));
}
#define CP_COMMIT() asm volatile("cp.async.commit_group;\n" ::: "memory")
#define CP_WAIT(n)  asm volatile("cp.async.wait_group %0;\n" :: "n"(n) : "memory")

// ---------------------------------------------------------------------------
// Tensor-core projection GEMM (bf16 3-term). MODE 0: head-permuted write with
// tf32 rounding (consumed by attn); MODE 1: row-major fp32 write.
// ---------------------------------------------------------------------------
template<int MODE>
__global__ void __launch_bounds__(256) gemm_tc(const float* __restrict__ Ain,
                                               const float* __restrict__ W,
                                               const float* __restrict__ bias,
                                               int outsel)
{
    const float* A = Ain ? Ain : g_ctx;
    float* out = (outsel == 0) ? g_qh : (outsel == 1) ? g_kh
               : (outsel == 2) ? g_vh : g_tmp;

    __shared__ __align__(16) __nv_bfloat16 sAhi[128][40];
    __shared__ __align__(16) __nv_bfloat16 sAlo[128][40];
    __shared__ __align__(16) __nv_bfloat16 sWhi[32][136];
    __shared__ __align__(16) __nv_bfloat16 sWlo[32][136];

    const int tid  = threadIdx.x;
    const int crow = blockIdx.y * 128;
    const int ccol = blockIdx.x * 128;

    const int warp = tid >> 5, lane = tid & 31;
    const int wm0 = (warp >> 1) * 32;
    const int wn0 = (warp & 1) * 64;
    const int gid = lane >> 2;
    const int qid = lane & 3;

    const int ar = tid >> 1;
    const int ac = (tid & 1) * 16;
    const int wr = tid >> 3;
    const int wc = (tid & 7) * 16;

    const float* Ap = A + (size_t)(crow + ar) * 1024 + ac;
    const float* Wp = W + (size_t)wr * 1024 + ccol + wc;

    float acc[2][8][4];
#pragma unroll
    for (int mt = 0; mt < 2; mt++)
#pragma unroll
        for (int nt = 0; nt < 8; nt++)
#pragma unroll
            for (int e = 0; e < 4; e++) acc[mt][nt][e] = 0.f;

    for (int k0 = 0; k0 < 1024; k0 += 32) {
        __syncthreads();
#pragma unroll
        for (int j = 0; j < 4; j++) {
            float4 v = *(const float4*)(Ap + k0 + 4 * j);
            float xs[4] = {v.x, v.y, v.z, v.w};
#pragma unroll
            for (int e = 0; e < 4; e++)
                splitf(xs[e], sAhi[ar][ac + 4*j + e], sAlo[ar][ac + 4*j + e]);
        }
#pragma unroll
        for (int j = 0; j < 4; j++) {
            float4 v = *(const float4*)(Wp + (size_t)k0 * 1024 + 4 * j);
            float xs[4] = {v.x, v.y, v.z, v.w};
#pragma unroll
            for (int e = 0; e < 4; e++)
                splitf(xs[e], sWhi[wr][wc + 4*j + e], sWlo[wr][wc + 4*j + e]);
        }
        __syncthreads();

#pragma unroll
        for (int ks = 0; ks < 32; ks += 16) {
            unsigned ahi[2][4], alo[2][4];
#pragma unroll
            for (int mt = 0; mt < 2; mt++) {
                const int r0 = wm0 + mt * 16 + gid;
                const int cc = ks + 2 * qid;
                ahi[mt][0] = *(const unsigned*)&sAhi[r0][cc];
                ahi[mt][1] = *(const unsigned*)&sAhi[r0 + 8][cc];
                ahi[mt][2] = *(const unsigned*)&sAhi[r0][cc + 8];
                ahi[mt][3] = *(const unsigned*)&sAhi[r0 + 8][cc + 8];
                alo[mt][0] = *(const unsigned*)&sAlo[r0][cc];
                alo[mt][1] = *(const unsigned*)&sAlo[r0 + 8][cc];
                alo[mt][2] = *(const unsigned*)&sAlo[r0][cc + 8];
                alo[mt][3] = *(const unsigned*)&sAlo[r0 + 8][cc + 8];
            }
#pragma unroll
            for (int nt = 0; nt < 8; nt++) {
                const int n  = wn0 + nt * 8 + gid;
                const int kk = ks + 2 * qid;
                unsigned bhi[2], blo[2];
                bhi[0] = (unsigned)__bfloat16_as_ushort(sWhi[kk][n])
                       | ((unsigned)__bfloat16_as_ushort(sWhi[kk + 1][n]) << 16);
                bhi[1] = (unsigned)__bfloat16_as_ushort(sWhi[kk + 8][n])
                       | ((unsigned)__bfloat16_as_ushort(sWhi[kk + 9][n]) << 16);
                blo[0] = (unsigned)__bfloat16_as_ushort(sWlo[kk][n])
                       | ((unsigned)__bfloat16_as_ushort(sWlo[kk + 1][n]) << 16);
                blo[1] = (unsigned)__bfloat16_as_ushort(sWlo[kk + 8][n])
                       | ((unsigned)__bfloat16_as_ushort(sWlo[kk + 9][n]) << 16);
#pragma unroll
                for (int mt = 0; mt < 2; mt++) {
                    bf16mma(acc[mt][nt], ahi[mt], bhi[0], bhi[1]);
                    bf16mma(acc[mt][nt], ahi[mt], blo[0], blo[1]);
                    bf16mma(acc[mt][nt], alo[mt], bhi[0], bhi[1]);
                }
            }
        }
    }

#pragma unroll
    for (int mt = 0; mt < 2; mt++) {
#pragma unroll
        for (int nt = 0; nt < 8; nt++) {
            const int row = crow + wm0 + mt * 16 + gid;
            const int col = ccol + wn0 + nt * 8 + 2 * qid;
            const float b0 = bias[col], b1 = bias[col + 1];
            float2 v0, v1;
            v0.x = acc[mt][nt][0] + b0; v0.y = acc[mt][nt][1] + b1;
            v1.x = acc[mt][nt][2] + b0; v1.y = acc[mt][nt][3] + b1;
            if (MODE == 1) {
                *(float2*)(out + (size_t)row * 1024 + col) = v0;
                *(float2*)(out + (size_t)(row + 8) * 1024 + col) = v1;
            } else {
                // tf32-round for the attention consumer
                v0.x = __uint_as_float(cvt_tf32(v0.x));
                v0.y = __uint_as_float(cvt_tf32(v0.y));
                v1.x = __uint_as_float(cvt_tf32(v1.x));
                v1.y = __uint_as_float(cvt_tf32(v1.y));
                const int b = row >> 11, h = col >> 6, d = col & 63;
                const int s = row & 2047;
                float* base = out + ((((size_t)b * Hc + h) * Sc) << 6) + d;
                *(float2*)(base + ((size_t)s << 6)) = v0;
                *(float2*)(base + ((size_t)(s + 8) << 6)) = v1;
            }
        }
    }
}

// ---------------------------------------------------------------------------
// Attention v3 (tf32, two-pass, normalized writes, cp.async double-buffered).
// Block = one (b,h) x 256 rows; 8 warps x 32 rows.
// ---------------------------------------------------------------------------
#define QSTf 68
#define KSTf 68
#define VSTf 72
#define OFF_Q 0
#define SZ_Q  (256*QSTf*4)
#define OFF_K (OFF_Q + SZ_Q)
#define SZ_K1 (128*KSTf*4)
#define OFF_V (OFF_K + 2*SZ_K1)
#define SZ_V1 (128*VSTf*4)
#define ATTN_SMEM (OFF_V + 2*SZ_V1)

__global__ void __launch_bounds__(256, 1) attn_tc(const int* __restrict__ isM,
                                                  float* __restrict__ attn_out)
{
    extern __shared__ char smraw[];
    const unsigned sbase = (unsigned)__cvta_generic_to_shared(smraw);
    const unsigned* Qs = (const unsigned*)(smraw + OFF_Q);
    const unsigned* Ks = (const unsigned*)(smraw + OFF_K);
    const unsigned* Vs = (const unsigned*)(smraw + OFF_V);

    const int tid = threadIdx.x;
    const int masked = *isM;
    const int i0 = (masked ? (gridDim.x - 1 - blockIdx.x) : blockIdx.x) * 256;
    const int h  = blockIdx.y;
    const int b  = blockIdx.z;

    const int warp = tid >> 5, lane = tid & 31;
    const int gid = lane >> 2, qid = lane & 3;

    const size_t bh = (size_t)b * Hc + h;
    const float* Qg = g_qh + bh * Sc * Dc + (size_t)i0 * Dc;
    const float* Kg = g_kh + bh * Sc * Dc;
    const float* Vg = g_vh + bh * Sc * Dc;

    int jmax = masked ? (i0 + 256) : Sc;
    const int ntiles = jmax >> 7;

    // ---- prologue: Q tile + K0/V0 via cp.async (group 0) ----
#pragma unroll
    for (int t = 0; t < 16; t++) {
        const int c = tid + t * 256;
        const int row = c >> 4, col4 = (c & 15) * 4;
        cpasync16(sbase + OFF_Q + (row * QSTf + col4) * 4, Qg + row * 64 + col4);
    }
#pragma unroll
    for (int t = 0; t < 8; t++) {
        const int c = tid + t * 256;
        const int row = c >> 4, col4 = (c & 15) * 4;
        cpasync16(sbase + OFF_K + (row * KSTf + col4) * 4, Kg + row * 64 + col4);
        cpasync16(sbase + OFF_V + (row * VSTf + col4) * 4, Vg + row * 64 + col4);
    }
    CP_COMMIT();

    float oacc[2][8][4];
#pragma unroll
    for (int mt = 0; mt < 2; mt++)
#pragma unroll
        for (int nt = 0; nt < 8; nt++)
#pragma unroll
            for (int e = 0; e < 4; e++) oacc[mt][nt][e] = 0.f;
    float lpa[4] = {0.f, 0.f, 0.f, 0.f};

    const int r0w = warp * 32;
    const unsigned l0s = (unsigned)((lane & 28) | (qid >> 1));
    const unsigned l2s = l0s | 2u;

    // =================== PASS A ===================
    for (int t = 0; t < ntiles; t++) {
        const int jt = t << 7;
        if (t + 1 < ntiles) {
            const float* Kn = Kg + (size_t)(jt + 128) * 64;
            const float* Vn = Vg + (size_t)(jt + 128) * 64;
            const unsigned kb = OFF_K + ((t + 1) & 1) * SZ_K1;
            const unsigned vb = OFF_V + ((t + 1) & 1) * SZ_V1;
#pragma unroll
            for (int tt = 0; tt < 8; tt++) {
                const int c = tid + tt * 256;
                const int row = c >> 4, col4 = (c & 15) * 4;
                cpasync16(sbase + kb + (row * KSTf + col4) * 4, Kn + row * 64 + col4);
                cpasync16(sbase + vb + (row * VSTf + col4) * 4, Vn + row * 64 + col4);
            }
            CP_COMMIT();
            CP_WAIT(1);
        } else {
            CP_WAIT(0);
        }
        __syncthreads();

        const unsigned* Kt = Ks + (t & 1) * (SZ_K1 / 4);
        const unsigned* Vt = Vs + (t & 1) * (SZ_V1 / 4);

#pragma unroll
        for (int half = 0; half < 2; half++) {
            float sacc[2][8][4];
#pragma unroll
            for (int mt = 0; mt < 2; mt++)
#pragma unroll
                for (int nt = 0; nt < 8; nt++)
#pragma unroll
                    for (int e = 0; e < 4; e++) sacc[mt][nt][e] = 0.f;

#pragma unroll
            for (int ks = 0; ks < 8; ks++) {
                unsigned qa[2][4];
#pragma unroll
                for (int mt = 0; mt < 2; mt++) {
                    const unsigned* q0 = Qs + (r0w + mt * 16 + gid) * QSTf + ks * 8;
                    const unsigned* q1 = q0 + 8 * QSTf;
                    qa[mt][0] = q0[qid];     qa[mt][1] = q1[qid];
                    qa[mt][2] = q0[qid + 4]; qa[mt][3] = q1[qid + 4];
                }
#pragma unroll
                for (int nt = 0; nt < 8; nt++) {
                    const unsigned* kr = Kt + (half * 64 + nt * 8 + gid) * KSTf + ks * 8;
                    const unsigned b0 = kr[qid], b1 = kr[qid + 4];
                    tf32mma(sacc[0][nt], qa[0], b0, b1);
                    tf32mma(sacc[1][nt], qa[1], b0, b1);
                }
            }

            // exp + sums + E@V per 8-col chunk
#pragma unroll
            for (int c = 0; c < 8; c++) {
                unsigned aE[2][4];
#pragma unroll
                for (int mt = 0; mt < 2; mt++) {
                    const int row0 = i0 + r0w + mt * 16 + gid;
                    const int row1 = row0 + 8;
                    const int jc = jt + half * 64 + c * 8 + 2 * qid;
                    float s0 = sacc[mt][c][0] * 0.125f;
                    float s1 = sacc[mt][c][1] * 0.125f;
                    float s2 = sacc[mt][c][2] * 0.125f;
                    float s3 = sacc[mt][c][3] * 0.125f;
                    if (masked) {
                        if (jc     > row0) s0 = -1e9f;
                        if (jc + 1 > row0) s1 = -1e9f;
                        if (jc     > row1) s2 = -1e9f;
                        if (jc + 1 > row1) s3 = -1e9f;
                    }
                    const float e0 = __expf(s0), e1 = __expf(s1);
                    const float e2 = __expf(s2), e3 = __expf(s3);
                    lpa[mt*2]     += e0 + e1;
                    lpa[mt*2 + 1] += e2 + e3;
                    float va, vb2;
                    va  = __shfl_sync(0xffffffffu, e0, l0s);
                    vb2 = __shfl_sync(0xffffffffu, e1, l0s);
                    aE[mt][0] = cvt_tf32((qid & 1) ? vb2 : va);
                    va  = __shfl_sync(0xffffffffu, e2, l0s);
                    vb2 = __shfl_sync(0xffffffffu, e3, l0s);
                    aE[mt][1] = cvt_tf32((qid & 1) ? vb2 : va);
                    va  = __shfl_sync(0xffffffffu, e0, l2s);
                    vb2 = __shfl_sync(0xffffffffu, e1, l2s);
                    aE[mt][2] = cvt_tf32((qid & 1) ? vb2 : va);
                    va  = __shfl_sync(0xffffffffu, e2, l2s);
                    vb2 = __shfl_sync(0xffffffffu, e3, l2s);
                    aE[mt][3] = cvt_tf32((qid & 1) ? vb2 : va);
                }
#pragma unroll
                for (int ntv = 0; ntv < 8; ntv++) {
                    const unsigned* vr0 = Vt + (half * 64 + c * 8 + qid) * VSTf + ntv * 8 + gid;
                    const unsigned b0 = vr0[0], b1 = vr0[4 * VSTf];
                    tf32mma(oacc[0][ntv], aE[0], b0, b1);
                    tf32mma(oacc[1][ntv], aE[1], b0, b1);
                }
            }
        }
        __syncthreads();
    }

    // ---- row sums -> inv; write ctx ----
    float inv[4];
#pragma unroll
    for (int r = 0; r < 4; r++) {
        float s = lpa[r];
        s += __shfl_xor_sync(0xffffffffu, s, 1);
        s += __shfl_xor_sync(0xffffffffu, s, 2);
        inv[r] = 1.f / s;
    }
    {
        float* ctx = g_ctx + ((size_t)b * Sc) * Ec + (size_t)h * Dc;
#pragma unroll
        for (int mt = 0; mt < 2; mt++) {
            const int row0 = i0 + r0w + mt * 16 + gid;
            const float iv0 = inv[mt*2], iv1 = inv[mt*2 + 1];
#pragma unroll
            for (int nt = 0; nt < 8; nt++) {
                const int col = nt * 8 + 2 * qid;
                float2 v0, v1;
                v0.x = oacc[mt][nt][0] * iv0; v0.y = oacc[mt][nt][1] * iv0;
                v1.x = oacc[mt][nt][2] * iv1; v1.y = oacc[mt][nt][3] * iv1;
                *(float2*)(ctx + (size_t)row0 * Ec + col) = v0;
                *(float2*)(ctx + (size_t)(row0 + 8) * Ec + col) = v1;
            }
        }
    }

    // =================== PASS B: recompute S, write normalized attn ===========
    {
#pragma unroll
        for (int tt = 0; tt < 8; tt++) {
            const int c = tid + tt * 256;
            const int row = c >> 4, col4 = (c & 15) * 4;
            cpasync16(sbase + OFF_K + (row * KSTf + col4) * 4, Kg + row * 64 + col4);
        }
        CP_COMMIT();
    }
    for (int t = 0; t < ntiles; t++) {
        const int jt = t << 7;
        if (t + 1 < ntiles) {
            const float* Kn = Kg + (size_t)(jt + 128) * 64;
            const unsigned kb = OFF_K + ((t + 1) & 1) * SZ_K1;
#pragma unroll
            for (int tt = 0; tt < 8; tt++) {
                const int c = tid + tt * 256;
                const int row = c >> 4, col4 = (c & 15) * 4;
                cpasync16(sbase + kb + (row * KSTf + col4) * 4, Kn + row * 64 + col4);
            }
            CP_COMMIT();
            CP_WAIT(1);
        } else {
            CP_WAIT(0);
        }
        __syncthreads();

        const unsigned* Kt = Ks + (t & 1) * (SZ_K1 / 4);

#pragma unroll
        for (int half = 0; half < 2; half++) {
            float sacc[2][8][4];
#pragma unroll
            for (int mt = 0; mt < 2; mt++)
#pragma unroll
                for (int nt = 0; nt < 8; nt++)
#pragma unroll
                    for (int e = 0; e < 4; e++) sacc[mt][nt][e] = 0.f;

#pragma unroll
            for (int ks = 0; ks < 8; ks++) {
                unsigned qa[2][4];
#pragma unroll
                for (int mt = 0; mt < 2; mt++) {
                    const unsigned* q0 = Qs + (r0w + mt * 16 + gid) * QSTf + ks * 8;
                    const unsigned* q1 = q0 + 8 * QSTf;
                    qa[mt][0] = q0[qid];     qa[mt][1] = q1[qid];
                    qa[mt][2] = q0[qid + 4]; qa[mt][3] = q1[qid + 4];
                }
#pragma unroll
                for (int nt = 0; nt < 8; nt++) {
                    const unsigned* kr = Kt + (half * 64 + nt * 8 + gid) * KSTf + ks * 8;
                    const unsigned b0 = kr[qid], b1 = kr[qid + 4];
                    tf32mma(sacc[0][nt], qa[0], b0, b1);
                    tf32mma(sacc[1][nt], qa[1], b0, b1);
                }
            }

#pragma unroll
            for (int nt = 0; nt < 8; nt++) {
#pragma unroll
                for (int mt = 0; mt < 2; mt++) {
                    const int row0 = i0 + r0w + mt * 16 + gid;
                    const int row1 = row0 + 8;
                    const int jc = jt + half * 64 + nt * 8 + 2 * qid;
                    float s0 = sacc[mt][nt][0] * 0.125f;
                    float s1 = sacc[mt][nt][1] * 0.125f;
                    float s2 = sacc[mt][nt][2] * 0.125f;
                    float s3 = sacc[mt][nt][3] * 0.125f;
                    if (masked) {
                        if (jc     > row0) s0 = -1e9f;
                        if (jc + 1 > row0) s1 = -1e9f;
                        if (jc     > row1) s2 = -1e9f;
                        if (jc + 1 > row1) s3 = -1e9f;
                    }
                    const float iv0 = inv[mt*2], iv1 = inv[mt*2 + 1];
                    float2 w0, w1;
                    w0.x = __expf(s0) * iv0; w0.y = __expf(s1) * iv0;
                    w1.x = __expf(s2) * iv1; w1.y = __expf(s3) * iv1;
                    *(float2*)(attn_out + (bh * Sc + row0) * Sc + jc) = w0;
                    *(float2*)(attn_out + (bh * Sc + row1) * Sc + jc) = w1;
                }
            }
        }
        __syncthreads();
    }

    // ---- zero-fill masked tail ----
    if (masked && jmax < Sc) {
        const int ncols = Sc - jmax;
        const float4 z = {0.f, 0.f, 0.f, 0.f};
        for (int r = warp; r < 256; r += 8) {
            float* rowp = attn_out + (bh * Sc + i0 + r) * Sc + jmax;
            for (int cz = lane * 4; cz < ncols; cz += 128)
                *(float4*)(rowp + cz) = z;
        }
    }
}

// ---------------------------------------------------------------------------
// Residual + LayerNorm
// ---------------------------------------------------------------------------
__global__ void __launch_bounds__(256) ln_kernel(const float* __restrict__ qin,
                                                 float* __restrict__ out)
{
    const size_t row = blockIdx.x;
    const int tid = threadIdx.x;
    float4 x  = *(const float4*)(g_tmp + row * 1024 + tid * 4);
    float4 qq = *(const float4*)(qin   + row * 1024 + tid * 4);
    x.x += qq.x; x.y += qq.y; x.z += qq.z; x.w += qq.w;

    float s  = x.x + x.y + x.z + x.w;
    float s2 = x.x*x.x + x.y*x.y + x.z*x.z + x.w*x.w;

    __shared__ float rs[8], rs2[8];
    const int w = tid >> 5, lane = tid & 31;
#pragma unroll
    for (int o = 16; o; o >>= 1) {
        s  += __shfl_xor_sync(0xffffffffu, s,  o);
        s2 += __shfl_xor_sync(0xffffffffu, s2, o);
    }
    if (!lane) { rs[w] = s; rs2[w] = s2; }
    __syncthreads();
    if (w == 0) {
        float a  = (lane < 8) ? rs[lane]  : 0.f;
        float a2 = (lane < 8) ? rs2[lane] : 0.f;
#pragma unroll
        for (int o = 4; o; o >>= 1) {
            a  += __shfl_xor_sync(0xffffffffu, a,  o);
            a2 += __shfl_xor_sync(0xffffffffu, a2, o);
        }
        if (!lane) { rs[0] = a; rs2[0] = a2; }
    }
    __syncthreads();
    const float mu   = rs[0] * (1.f / 1024.f);
    const float var  = rs2[0] * (1.f / 1024.f) - mu * mu;
    const float rstd = rsqrtf(var + 1e-5f);
    float4 o;
    o.x = (x.x - mu) * rstd; o.y = (x.y - mu) * rstd;
    o.z = (x.z - mu) * rstd; o.w = (x.w - mu) * rstd;
    *(float4*)(out + row * 1024 + tid * 4) = o;
}

// ---------------------------------------------------------------------------
extern "C" void kernel_launch(void* const* d_in, const int* in_sizes, int n_in,
                              void* d_out, int out_size)
{
    (void)in_sizes; (void)n_in; (void)out_size;
    const float* q  = (const float*)d_in[0];
    const float* k  = (const float*)d_in[1];
    const float* v  = (const float*)d_in[2];
    const float* Wq = (const float*)d_in[3];
    const float* bq = (const float*)d_in[4];
    const float* Wk = (const float*)d_in[5];
    const float* bk = (const float*)d_in[6];
    const float* Wv = (const float*)d_in[7];
    const float* bv = (const float*)d_in[8];
    const float* Wo = (const float*)d_in[9];
    const float* bo = (const float*)d_in[10];
    const int*   isM = (const int*)d_in[11];

    float* out  = (float*)d_out;
    float* attn = out + (size_t)Bc * Sc * Ec;

    cudaFuncSetAttribute(attn_tc,
                         cudaFuncAttributeMaxDynamicSharedMemorySize, ATTN_SMEM);

    dim3 gg(Ec / 128, M_TOT / 128);
    gemm_tc<0><<<gg, 256>>>(q, Wq, bq, 0);
    gemm_tc<0><<<gg, 256>>>(k, Wk, bk, 1);
    gemm_tc<0><<<gg, 256>>>(v, Wv, bv, 2);

    attn_tc<<<dim3(Sc / 256, Hc, Bc), 256, ATTN_SMEM>>>(isM, attn);

    gemm_tc<1><<<gg, 256>>>(nullptr, Wo, bo, 3);
    ln_kernel<<<M_TOT, 256>>>(q, out);
}

// round 6
// speedup vs baseline: 3.7431x; 1.3518x over previous
#include <cuda_runtime.h>
#include <cuda_bf16.h>
#include <cstddef>

// Problem constants
#define Bc 2
#define Sc 2048
#define Ec 1024
#define Hc 16
#define Dc 64
#define M_TOT (Bc*Sc)

// Scratch (device globals)
__device__ float g_qh[(size_t)Bc*Hc*Sc*Dc];            // [b,h,s,d] tf32, pre-scaled by 1/8
__device__ float g_kh[(size_t)Bc*Hc*Sc*Dc];            // [b,h,s,d] tf32
__device__ __nv_bfloat16 g_vhi[(size_t)Bc*Hc*Sc*Dc];   // V hi (bf16 split)
__device__ __nv_bfloat16 g_vlo[(size_t)Bc*Hc*Sc*Dc];   // V lo
__device__ float g_ctx[(size_t)Bc*Sc*Ec];              // [b,s,h*d]
__device__ float g_tmp[(size_t)Bc*Sc*Ec];              // pre-LN output

// ---------------- helpers ----------------
__device__ __forceinline__ void bf16mma(float c[4], const unsigned a[4],
                                        unsigned b0, unsigned b1)
{
    asm volatile(
        "mma.sync.aligned.m16n8k16.row.col.f32.bf16.bf16.f32 "
        "{%0,%1,%2,%3}, {%4,%5,%6,%7}, {%8,%9}, {%0,%1,%2,%3};\n"
        : "+f"(c[0]), "+f"(c[1]), "+f"(c[2]), "+f"(c[3])
        : "r"(a[0]), "r"(a[1]), "r"(a[2]), "r"(a[3]), "r"(b0), "r"(b1));
}

__device__ __forceinline__ void tf32mma(float c[4], const unsigned a[4],
                                        unsigned b0, unsigned b1)
{
    asm volatile(
        "mma.sync.aligned.m16n8k8.row.col.f32.tf32.tf32.f32 "
        "{%0,%1,%2,%3}, {%4,%5,%6,%7}, {%8,%9}, {%0,%1,%2,%3};\n"
        : "+f"(c[0]), "+f"(c[1]), "+f"(c[2]), "+f"(c[3])
        : "r"(a[0]), "r"(a[1]), "r"(a[2]), "r"(a[3]), "r"(b0), "r"(b1));
}

__device__ __forceinline__ unsigned cvt_tf32(float x)
{
    unsigned r;
    asm("cvt.rna.tf32.f32 %0, %1;" : "=r"(r) : "f"(x));
    return r;
}

// pack two floats into bf16x2 hi word and residual lo word
__device__ __forceinline__ void split2pack(float a, float b, unsigned& hi, unsigned& lo)
{
    __nv_bfloat16 ha = __float2bfloat16(a), hb = __float2bfloat16(b);
    __nv_bfloat16 la = __float2bfloat16(a - __bfloat162float(ha));
    __nv_bfloat16 lb = __float2bfloat16(b - __bfloat162float(hb));
    hi = (unsigned)__bfloat16_as_ushort(ha) | ((unsigned)__bfloat16_as_ushort(hb) << 16);
    lo = (unsigned)__bfloat16_as_ushort(la) | ((unsigned)__bfloat16_as_ushort(lb) << 16);
}

__device__ __forceinline__ void ldmx4t(unsigned addr, unsigned r[4])
{
    asm volatile("ldmatrix.sync.aligned.m8n8.x4.trans.shared.b16 {%0,%1,%2,%3}, [%4];"
                 : "=r"(r[0]), "=r"(r[1]), "=r"(r[2]), "=r"(r[3]) : "r"(addr));
}

__device__ __forceinline__ void cpasync16(unsigned s, const void* g)
{
    asm volatile("cp.async.cg.shared.global [%0], [%1], 16;\n" :: "r"(s), "l"(g));
}
#define CP_COMMIT() asm volatile("cp.async.commit_group;\n" ::: "memory")
#define CP_WAIT(n)  asm volatile("cp.async.wait_group %0;\n" :: "n"(n) : "memory")

// ---------------------------------------------------------------------------
// tf32 single-term GEMM, cp.async double-buffered. C[4096,1024] = A@W + bias.
// BM=128 BN=128 BK=32; 256 thr, 8 warps (4x2), warp 32x64, mma m16n8k8.
// MODE 0: head-permuted writes (Q: *0.125+tf32; K: tf32; V: bf16 hi/lo split)
// MODE 1: plain row-major fp32 (out-proj -> g_tmp)
// ---------------------------------------------------------------------------
#define GA_ST 36
#define GW_ST 136
#define G_SZA (128*GA_ST*4)
#define G_SZW (32*GW_ST*4)
#define GEMM_SMEM (2*G_SZA + 2*G_SZW)

template<int MODE>
__global__ void __launch_bounds__(256) gemm_tf32(const float* __restrict__ Ain,
                                                 const float* __restrict__ W,
                                                 const float* __restrict__ bias,
                                                 int outsel)
{
    extern __shared__ char gsm[];
    const unsigned sb = (unsigned)__cvta_generic_to_shared(gsm);
    const float* sA = (const float*)gsm;
    const float* sW = (const float*)(gsm + 2*G_SZA);

    const float* A = Ain ? Ain : g_ctx;
    const int tid  = threadIdx.x;
    const int crow = blockIdx.y * 128;
    const int ccol = blockIdx.x * 128;

    const int warp = tid >> 5, lane = tid & 31;
    const int wm0 = (warp >> 1) * 32;
    const int wn0 = (warp & 1) * 64;
    const int gid = lane >> 2;
    const int qid = lane & 3;

    float acc[2][8][4];
#pragma unroll
    for (int mt = 0; mt < 2; mt++)
#pragma unroll
        for (int nt = 0; nt < 8; nt++)
#pragma unroll
            for (int e = 0; e < 4; e++) acc[mt][nt][e] = 0.f;

    // cp.async mappings (4 chunks each for A and W per thread)
    // A: chunk c: row=c>>3 (0..127), col=(c&7)*4 of 32
    // W: chunk c: row=c>>5 (0..31),  col=(c&31)*4 of 128
    auto issueA = [&](int t, int buf) {
        const float* Ag = A + (size_t)crow * 1024 + t * 32;
        const unsigned sbA = sb + buf * G_SZA;
#pragma unroll
        for (int j = 0; j < 4; j++) {
            const int c = tid + j * 256;
            const int row = c >> 3, col = (c & 7) * 4;
            cpasync16(sbA + (row * GA_ST + col) * 4, Ag + (size_t)row * 1024 + col);
        }
    };
    auto issueW = [&](int t, int buf) {
        const float* Wg = W + (size_t)t * 32 * 1024 + ccol;
        const unsigned sbW = sb + 2*G_SZA + buf * G_SZW;
#pragma unroll
        for (int j = 0; j < 4; j++) {
            const int c = tid + j * 256;
            const int row = c >> 5, col = (c & 31) * 4;
            cpasync16(sbW + (row * GW_ST + col) * 4, Wg + (size_t)row * 1024 + col);
        }
    };

    issueA(0, 0); issueW(0, 0); CP_COMMIT();

    for (int t = 0; t < 32; t++) {
        if (t + 1 < 32) {
            issueA(t + 1, (t + 1) & 1);
            issueW(t + 1, (t + 1) & 1);
            CP_COMMIT();
            CP_WAIT(1);
        } else {
            CP_WAIT(0);
        }
        __syncthreads();

        const float* At = sA + (t & 1) * (G_SZA / 4);
        const float* Wt = sW + (t & 1) * (G_SZW / 4);

#pragma unroll
        for (int ks = 0; ks < 4; ks++) {
            unsigned a[2][4];
#pragma unroll
            for (int mt = 0; mt < 2; mt++) {
                const float* p = At + (wm0 + mt * 16 + gid) * GA_ST + ks * 8;
                a[mt][0] = cvt_tf32(p[qid]);
                a[mt][1] = cvt_tf32(p[8 * GA_ST + qid]);
                a[mt][2] = cvt_tf32(p[qid + 4]);
                a[mt][3] = cvt_tf32(p[8 * GA_ST + qid + 4]);
            }
#pragma unroll
            for (int nt = 0; nt < 8; nt++) {
                const int n = wn0 + nt * 8 + gid;
                const unsigned b0 = cvt_tf32(Wt[(ks * 8 + qid) * GW_ST + n]);
                const unsigned b1 = cvt_tf32(Wt[(ks * 8 + qid + 4) * GW_ST + n]);
                tf32mma(acc[0][nt], a[0], b0, b1);
                tf32mma(acc[1][nt], a[1], b0, b1);
            }
        }
        __syncthreads();
    }

    const float qscale = (MODE == 0 && outsel == 0) ? 0.125f : 1.0f;
#pragma unroll
    for (int mt = 0; mt < 2; mt++) {
#pragma unroll
        for (int nt = 0; nt < 8; nt++) {
            const int row = crow + wm0 + mt * 16 + gid;
            const int col = ccol + wn0 + nt * 8 + 2 * qid;
            const float b0 = bias[col], b1 = bias[col + 1];
            float2 v0, v1;
            v0.x = acc[mt][nt][0] + b0; v0.y = acc[mt][nt][1] + b1;
            v1.x = acc[mt][nt][2] + b0; v1.y = acc[mt][nt][3] + b1;
            if (MODE == 1) {
                *(float2*)(g_tmp + (size_t)row * 1024 + col) = v0;
                *(float2*)(g_tmp + (size_t)(row + 8) * 1024 + col) = v1;
            } else {
                const int bb = row >> 11, hh = col >> 6, d = col & 63;
                const int s = row & 2047;
                const size_t base = ((((size_t)bb * Hc + hh) * Sc + s) << 6) + d;
                if (outsel == 2) {
                    unsigned hi, lo;
                    split2pack(v0.x, v0.y, hi, lo);
                    *(unsigned*)&g_vhi[base] = hi;
                    *(unsigned*)&g_vlo[base] = lo;
                    split2pack(v1.x, v1.y, hi, lo);
                    *(unsigned*)&g_vhi[base + (8 << 6)] = hi;
                    *(unsigned*)&g_vlo[base + (8 << 6)] = lo;
                } else {
                    float* out = outsel ? g_kh : g_qh;
                    float2 w0, w1;
                    w0.x = __uint_as_float(cvt_tf32(v0.x * qscale));
                    w0.y = __uint_as_float(cvt_tf32(v0.y * qscale));
                    w1.x = __uint_as_float(cvt_tf32(v1.x * qscale));
                    w1.y = __uint_as_float(cvt_tf32(v1.y * qscale));
                    *(float2*)(out + base) = w0;
                    *(float2*)(out + base + (8 << 6)) = w1;
                }
            }
        }
    }
}

// ---------------------------------------------------------------------------
// Attention v4: tf32 QK (operands pre-rounded, Q pre-scaled), bf16 3-term E@V
// built directly from C-fragments (no shuffles), two-pass normalized writes,
// cp.async double-buffered K (fp32) + V (bf16 hi/lo).
// Block = one (b,h) x 256 rows; 8 warps x 32 rows.
// ---------------------------------------------------------------------------
#define QSTf 68
#define KSTf 68
#define VSTB 72
#define OFF_Q 0
#define SZ_Q   (256*QSTf*4)
#define OFF_K  (OFF_Q + SZ_Q)
#define SZ_K1  (128*KSTf*4)
#define OFF_VH (OFF_K + 2*SZ_K1)
#define SZ_V1B (128*VSTB*2)
#define ATTN_SMEM (OFF_VH + 4*SZ_V1B)

__global__ void __launch_bounds__(256, 1) attn_tc(const int* __restrict__ isM,
                                                  float* __restrict__ attn_out)
{
    extern __shared__ char smraw[];
    const unsigned sbase = (unsigned)__cvta_generic_to_shared(smraw);
    const unsigned* Qs = (const unsigned*)(smraw + OFF_Q);
    const unsigned* Ks = (const unsigned*)(smraw + OFF_K);

    const int tid = threadIdx.x;
    const int masked = *isM;
    const int i0 = (masked ? (gridDim.x - 1 - blockIdx.x) : blockIdx.x) * 256;
    const int h  = blockIdx.y;
    const int b  = blockIdx.z;

    const int warp = tid >> 5, lane = tid & 31;
    const int gid = lane >> 2, qid = lane & 3;
    const int grp = lane >> 3, li = lane & 7;

    const size_t bh = (size_t)b * Hc + h;
    const float* Qg = g_qh + bh * Sc * Dc + (size_t)i0 * Dc;
    const float* Kg = g_kh + bh * Sc * Dc;
    const __nv_bfloat16* Vhg = g_vhi + bh * Sc * Dc;
    const __nv_bfloat16* Vlg = g_vlo + bh * Sc * Dc;

    const int jmax = masked ? (i0 + 256) : Sc;
    const int ntiles = jmax >> 7;

    // per-lane ldmatrix.trans offset for V (row-major bf16, stride VSTB)
    const unsigned offV = (unsigned)(((li + ((grp & 1) << 3)) * VSTB + ((grp >> 1) << 3)) * 2);

    // ---- prologue: Q + K0 + V0 ----
#pragma unroll
    for (int t = 0; t < 16; t++) {
        const int c = tid + t * 256;
        const int row = c >> 4, col4 = (c & 15) * 4;
        cpasync16(sbase + OFF_Q + (row * QSTf + col4) * 4, Qg + row * 64 + col4);
    }
#pragma unroll
    for (int t = 0; t < 8; t++) {
        const int c = tid + t * 256;
        const int row = c >> 4, col4 = (c & 15) * 4;
        cpasync16(sbase + OFF_K + (row * KSTf + col4) * 4, Kg + row * 64 + col4);
    }
#pragma unroll
    for (int t = 0; t < 4; t++) {
        const int c = tid + t * 256;
        const int row = c >> 3, col8 = (c & 7) * 8;
        cpasync16(sbase + OFF_VH + (row * VSTB + col8) * 2, Vhg + row * 64 + col8);
        cpasync16(sbase + OFF_VH + SZ_V1B + (row * VSTB + col8) * 2, Vlg + row * 64 + col8);
    }
    CP_COMMIT();

    float oacc[2][8][4];
#pragma unroll
    for (int mt = 0; mt < 2; mt++)
#pragma unroll
        for (int nt = 0; nt < 8; nt++)
#pragma unroll
            for (int e = 0; e < 4; e++) oacc[mt][nt][e] = 0.f;
    float lpa[4] = {0.f, 0.f, 0.f, 0.f};

    const int r0w = warp * 32;

    // =================== PASS A: sums + ctx ===================
    for (int t = 0; t < ntiles; t++) {
        const int jt = t << 7;
        if (t + 1 < ntiles) {
            const float* Kn = Kg + (size_t)(jt + 128) * 64;
            const __nv_bfloat16* Vhn = Vhg + (size_t)(jt + 128) * 64;
            const __nv_bfloat16* Vln = Vlg + (size_t)(jt + 128) * 64;
            const unsigned kb = OFF_K + ((t + 1) & 1) * SZ_K1;
            const unsigned vb = OFF_VH + ((t + 1) & 1) * 2 * SZ_V1B;
#pragma unroll
            for (int tt = 0; tt < 8; tt++) {
                const int c = tid + tt * 256;
                const int row = c >> 4, col4 = (c & 15) * 4;
                cpasync16(sbase + kb + (row * KSTf + col4) * 4, Kn + row * 64 + col4);
            }
#pragma unroll
            for (int tt = 0; tt < 4; tt++) {
                const int c = tid + tt * 256;
                const int row = c >> 3, col8 = (c & 7) * 8;
                cpasync16(sbase + vb + (row * VSTB + col8) * 2, Vhn + row * 64 + col8);
                cpasync16(sbase + vb + SZ_V1B + (row * VSTB + col8) * 2, Vln + row * 64 + col8);
            }
            CP_COMMIT();
            CP_WAIT(1);
        } else {
            CP_WAIT(0);
        }
        __syncthreads();

        const unsigned* Kt = Ks + (t & 1) * (SZ_K1 / 4);
        const unsigned vh_s = sbase + OFF_VH + (t & 1) * 2 * SZ_V1B;
        const unsigned vl_s = vh_s + SZ_V1B;

#pragma unroll
        for (int half = 0; half < 2; half++) {
            // ---- S = Q K^T (tf32), 32 rows x 64 cols ----
            float sacc[2][8][4];
#pragma unroll
            for (int mt = 0; mt < 2; mt++)
#pragma unroll
                for (int nt = 0; nt < 8; nt++)
#pragma unroll
                    for (int e = 0; e < 4; e++) sacc[mt][nt][e] = 0.f;

#pragma unroll
            for (int ks = 0; ks < 8; ks++) {
                unsigned qa[2][4];
#pragma unroll
                for (int mt = 0; mt < 2; mt++) {
                    const unsigned* q0 = Qs + (r0w + mt * 16 + gid) * QSTf + ks * 8;
                    qa[mt][0] = q0[qid];            qa[mt][1] = q0[8 * QSTf + qid];
                    qa[mt][2] = q0[qid + 4];        qa[mt][3] = q0[8 * QSTf + qid + 4];
                }
#pragma unroll
                for (int nt = 0; nt < 8; nt++) {
                    const unsigned* kr = Kt + (half * 64 + nt * 8 + gid) * KSTf + ks * 8;
                    const unsigned b0 = kr[qid], b1 = kr[qid + 4];
                    tf32mma(sacc[0][nt], qa[0], b0, b1);
                    tf32mma(sacc[1][nt], qa[1], b0, b1);
                }
            }

            // ---- exp + row sums + E@V (bf16 3-term from C-frags) ----
#pragma unroll
            for (int c = 0; c < 4; c++) {
                unsigned aEh[2][4], aEl[2][4];
#pragma unroll
                for (int mt = 0; mt < 2; mt++) {
                    const int row0 = i0 + r0w + mt * 16 + gid;
                    const int row1 = row0 + 8;
                    const int jc0 = jt + half * 64 + c * 16 + 2 * qid;
                    const int jc1 = jc0 + 8;
                    float s00 = sacc[mt][2*c][0],   s01 = sacc[mt][2*c][1];
                    float s10 = sacc[mt][2*c][2],   s11 = sacc[mt][2*c][3];
                    float f00 = sacc[mt][2*c+1][0], f01 = sacc[mt][2*c+1][1];
                    float f10 = sacc[mt][2*c+1][2], f11 = sacc[mt][2*c+1][3];
                    if (masked) {
                        if (jc0     > row0) s00 = -1e9f;
                        if (jc0 + 1 > row0) s01 = -1e9f;
                        if (jc0     > row1) s10 = -1e9f;
                        if (jc0 + 1 > row1) s11 = -1e9f;
                        if (jc1     > row0) f00 = -1e9f;
                        if (jc1 + 1 > row0) f01 = -1e9f;
                        if (jc1     > row1) f10 = -1e9f;
                        if (jc1 + 1 > row1) f11 = -1e9f;
                    }
                    const float e00 = __expf(s00), e01 = __expf(s01);
                    const float e10 = __expf(s10), e11 = __expf(s11);
                    const float g00 = __expf(f00), g01 = __expf(f01);
                    const float g10 = __expf(f10), g11 = __expf(f11);
                    lpa[mt*2]     += e00 + e01 + g00 + g01;
                    lpa[mt*2 + 1] += e10 + e11 + g10 + g11;
                    split2pack(e00, e01, aEh[mt][0], aEl[mt][0]);
                    split2pack(e10, e11, aEh[mt][1], aEl[mt][1]);
                    split2pack(g00, g01, aEh[mt][2], aEl[mt][2]);
                    split2pack(g10, g11, aEh[mt][3], aEl[mt][3]);
                }
#pragma unroll
                for (int ntp = 0; ntp < 4; ntp++) {
                    unsigned vbH[4], vbL[4];
                    const unsigned voff = (unsigned)((half * 64 + c * 16) * VSTB * 2 + ntp * 32) + offV;
                    ldmx4t(vh_s + voff, vbH);
                    ldmx4t(vl_s + voff, vbL);
#pragma unroll
                    for (int mt = 0; mt < 2; mt++) {
                        bf16mma(oacc[mt][2*ntp],   aEh[mt], vbH[0], vbH[1]);
                        bf16mma(oacc[mt][2*ntp],   aEh[mt], vbL[0], vbL[1]);
                        bf16mma(oacc[mt][2*ntp],   aEl[mt], vbH[0], vbH[1]);
                        bf16mma(oacc[mt][2*ntp+1], aEh[mt], vbH[2], vbH[3]);
                        bf16mma(oacc[mt][2*ntp+1], aEh[mt], vbL[2], vbL[3]);
                        bf16mma(oacc[mt][2*ntp+1], aEl[mt], vbH[2], vbH[3]);
                    }
                }
            }
        }
        __syncthreads();
    }

    // ---- row sums -> inv; write ctx ----
    float inv[4];
#pragma unroll
    for (int r = 0; r < 4; r++) {
        float s = lpa[r];
        s += __shfl_xor_sync(0xffffffffu, s, 1);
        s += __shfl_xor_sync(0xffffffffu, s, 2);
        inv[r] = 1.f / s;
    }
    {
        float* ctx = g_ctx + ((size_t)b * Sc) * Ec + (size_t)h * Dc;
#pragma unroll
        for (int mt = 0; mt < 2; mt++) {
            const int row0 = i0 + r0w + mt * 16 + gid;
            const float iv0 = inv[mt*2], iv1 = inv[mt*2 + 1];
#pragma unroll
            for (int nt = 0; nt < 8; nt++) {
                const int col = nt * 8 + 2 * qid;
                float2 v0, v1;
                v0.x = oacc[mt][nt][0] * iv0; v0.y = oacc[mt][nt][1] * iv0;
                v1.x = oacc[mt][nt][2] * iv1; v1.y = oacc[mt][nt][3] * iv1;
                *(float2*)(ctx + (size_t)row0 * Ec + col) = v0;
                *(float2*)(ctx + (size_t)(row0 + 8) * Ec + col) = v1;
            }
        }
    }

    // =================== PASS B: recompute S, write normalized attn ==========
    {
#pragma unroll
        for (int tt = 0; tt < 8; tt++) {
            const int c = tid + tt * 256;
            const int row = c >> 4, col4 = (c & 15) * 4;
            cpasync16(sbase + OFF_K + (row * KSTf + col4) * 4, Kg + row * 64 + col4);
        }
        CP_COMMIT();
    }
    for (int t = 0; t < ntiles; t++) {
        const int jt = t << 7;
        if (t + 1 < ntiles) {
            const float* Kn = Kg + (size_t)(jt + 128) * 64;
            const unsigned kb = OFF_K + ((t + 1) & 1) * SZ_K1;
#pragma unroll
            for (int tt = 0; tt < 8; tt++) {
                const int c = tid + tt * 256;
                const int row = c >> 4, col4 = (c & 15) * 4;
                cpasync16(sbase + kb + (row * KSTf + col4) * 4, Kn + row * 64 + col4);
            }
            CP_COMMIT();
            CP_WAIT(1);
        } else {
            CP_WAIT(0);
        }
        __syncthreads();

        const unsigned* Kt = Ks + (t & 1) * (SZ_K1 / 4);

#pragma unroll
        for (int half = 0; half < 2; half++) {
            float sacc[2][8][4];
#pragma unroll
            for (int mt = 0; mt < 2; mt++)
#pragma unroll
                for (int nt = 0; nt < 8; nt++)
#pragma unroll
                    for (int e = 0; e < 4; e++) sacc[mt][nt][e] = 0.f;

#pragma unroll
            for (int ks = 0; ks < 8; ks++) {
                unsigned qa[2][4];
#pragma unroll
                for (int mt = 0; mt < 2; mt++) {
                    const unsigned* q0 = Qs + (r0w + mt * 16 + gid) * QSTf + ks * 8;
                    qa[mt][0] = q0[qid];            qa[mt][1] = q0[8 * QSTf + qid];
                    qa[mt][2] = q0[qid + 4];        qa[mt][3] = q0[8 * QSTf + qid + 4];
                }
#pragma unroll
                for (int nt = 0; nt < 8; nt++) {
                    const unsigned* kr = Kt + (half * 64 + nt * 8 + gid) * KSTf + ks * 8;
                    const unsigned b0 = kr[qid], b1 = kr[qid + 4];
                    tf32mma(sacc[0][nt], qa[0], b0, b1);
                    tf32mma(sacc[1][nt], qa[1], b0, b1);
                }
            }

#pragma unroll
            for (int nt = 0; nt < 8; nt++) {
#pragma unroll
                for (int mt = 0; mt < 2; mt++) {
                    const int row0 = i0 + r0w + mt * 16 + gid;
                    const int row1 = row0 + 8;
                    const int jc = jt + half * 64 + nt * 8 + 2 * qid;
                    float s0 = sacc[mt][nt][0];
                    float s1 = sacc[mt][nt][1];
                    float s2 = sacc[mt][nt][2];
                    float s3 = sacc[mt][nt][3];
                    if (masked) {
                        if (jc     > row0) s0 = -1e9f;
                        if (jc + 1 > row0) s1 = -1e9f;
                        if (jc     > row1) s2 = -1e9f;
                        if (jc + 1 > row1) s3 = -1e9f;
                    }
                    const float iv0 = inv[mt*2], iv1 = inv[mt*2 + 1];
                    float2 w0, w1;
                    w0.x = __expf(s0) * iv0; w0.y = __expf(s1) * iv0;
                    w1.x = __expf(s2) * iv1; w1.y = __expf(s3) * iv1;
                    *(float2*)(attn_out + (bh * Sc + row0) * Sc + jc) = w0;
                    *(float2*)(attn_out + (bh * Sc + row1) * Sc + jc) = w1;
                }
            }
        }
        __syncthreads();
    }

    // ---- zero-fill masked tail ----
    if (masked && jmax < Sc) {
        const int ncols = Sc - jmax;
        const float4 z = {0.f, 0.f, 0.f, 0.f};
        for (int r = warp; r < 256; r += 8) {
            float* rowp = attn_out + (bh * Sc + i0 + r) * Sc + jmax;
            for (int cz = lane * 4; cz < ncols; cz += 128)
                *(float4*)(rowp + cz) = z;
        }
    }
}

// ---------------------------------------------------------------------------
// Residual + LayerNorm
// ---------------------------------------------------------------------------
__global__ void __launch_bounds__(256) ln_kernel(const float* __restrict__ qin,
                                                 float* __restrict__ out)
{
    const size_t row = blockIdx.x;
    const int tid = threadIdx.x;
    float4 x  = *(const float4*)(g_tmp + row * 1024 + tid * 4);
    float4 qq = *(const float4*)(qin   + row * 1024 + tid * 4);
    x.x += qq.x; x.y += qq.y; x.z += qq.z; x.w += qq.w;

    float s  = x.x + x.y + x.z + x.w;
    float s2 = x.x*x.x + x.y*x.y + x.z*x.z + x.w*x.w;

    __shared__ float rs[8], rs2[8];
    const int w = tid >> 5, lane = tid & 31;
#pragma unroll
    for (int o = 16; o; o >>= 1) {
        s  += __shfl_xor_sync(0xffffffffu, s,  o);
        s2 += __shfl_xor_sync(0xffffffffu, s2, o);
    }
    if (!lane) { rs[w] = s; rs2[w] = s2; }
    __syncthreads();
    if (w == 0) {
        float a  = (lane < 8) ? rs[lane]  : 0.f;
        float a2 = (lane < 8) ? rs2[lane] : 0.f;
#pragma unroll
        for (int o = 4; o; o >>= 1) {
            a  += __shfl_xor_sync(0xffffffffu, a,  o);
            a2 += __shfl_xor_sync(0xffffffffu, a2, o);
        }
        if (!lane) { rs[0] = a; rs2[0] = a2; }
    }
    __syncthreads();
    const float mu   = rs[0] * (1.f / 1024.f);
    const float var  = rs2[0] * (1.f / 1024.f) - mu * mu;
    const float rstd = rsqrtf(var + 1e-5f);
    float4 o;
    o.x = (x.x - mu) * rstd; o.y = (x.y - mu) * rstd;
    o.z = (x.z - mu) * rstd; o.w = (x.w - mu) * rstd;
    *(float4*)(out + row * 1024 + tid * 4) = o;
}

// ---------------------------------------------------------------------------
extern "C" void kernel_launch(void* const* d_in, const int* in_sizes, int n_in,
                              void* d_out, int out_size)
{
    (void)in_sizes; (void)n_in; (void)out_size;
    const float* q  = (const float*)d_in[0];
    const float* k  = (const float*)d_in[1];
    const float* v  = (const float*)d_in[2];
    const float* Wq = (const float*)d_in[3];
    const float* bq = (const float*)d_in[4];
    const float* Wk = (const float*)d_in[5];
    const float* bk = (const float*)d_in[6];
    const float* Wv = (const float*)d_in[7];
    const float* bv = (const float*)d_in[8];
    const float* Wo = (const float*)d_in[9];
    const float* bo = (const float*)d_in[10];
    const int*   isM = (const int*)d_in[11];

    float* out  = (float*)d_out;
    float* attn = out + (size_t)Bc * Sc * Ec;

    cudaFuncSetAttribute(attn_tc,
                         cudaFuncAttributeMaxDynamicSharedMemorySize, ATTN_SMEM);
    cudaFuncSetAttribute(gemm_tf32<0>,
                         cudaFuncAttributeMaxDynamicSharedMemorySize, GEMM_SMEM);
    cudaFuncSetAttribute(gemm_tf32<1>,
                         cudaFuncAttributeMaxDynamicSharedMemorySize, GEMM_SMEM);

    dim3 gg(Ec / 128, M_TOT / 128);
    gemm_tf32<0><<<gg, 256, GEMM_SMEM>>>(q, Wq, bq, 0);
    gemm_tf32<0><<<gg, 256, GEMM_SMEM>>>(k, Wk, bk, 1);
    gemm_tf32<0><<<gg, 256, GEMM_SMEM>>>(v, Wv, bv, 2);

    attn_tc<<<dim3(Sc / 256, Hc, Bc), 256, ATTN_SMEM>>>(isM, attn);

    gemm_tf32<1><<<gg, 256, GEMM_SMEM>>>(nullptr, Wo, bo, 3);
    ln_kernel<<<M_TOT, 256>>>(q, out);
}